// round 1
// baseline (speedup 1.0000x reference)
#include <cuda_runtime.h>

#define BB 4
#define CHC 64
#define HH 128
#define WW 128
#define HWS (HH*WW)

// ---------------- scratch (no allocations allowed) ----------------
__device__ float d_nbhT[BB*HWS*CHC];   // NHWC nbh
__device__ float d_cenT[BB*HWS*CHC];   // NHWC cen
__device__ float d_gT  [BB*HWS*CHC];   // conv(nbh, w1a) NHWC
__device__ float d_cT  [BB*HWS*CHC];   // conv(cen, w1c) NHWC
__device__ float d_outT[BB*HWS*CHC];   // NHWC output
__device__ float d_w1a [CHC*9*CHC];    // [c][k][o-swizzled]
__device__ float d_w1c [CHC*9*CHC];

// ---------------- transpose: in [batch][R][C] -> out [batch][C][R] ----------------
__global__ void transpose_k(const float* __restrict__ in, float* __restrict__ out,
                            int R, int C)
{
    __shared__ float tile[32][33];
    int b = blockIdx.z;
    const float* inb = in + (size_t)b * R * C;
    float* outb = out + (size_t)b * R * C;
    int c0 = blockIdx.x * 32;
    int r0 = blockIdx.y * 32;
#pragma unroll
    for (int i = 0; i < 32; i += 8)
        tile[threadIdx.y + i][threadIdx.x] =
            inb[(size_t)(r0 + threadIdx.y + i) * C + (c0 + threadIdx.x)];
    __syncthreads();
#pragma unroll
    for (int i = 0; i < 32; i += 8)
        outb[(size_t)(c0 + threadIdx.y + i) * R + (r0 + threadIdx.x)] =
            tile[threadIdx.x][threadIdx.y + i];
}

// ---------------- weight prep: w1[64,1152] -> [c][k][o-swizzled] halves ----------------
// swizzle: o = og*16 + j*4 + m stored at float position (j*4+og)*4 + m
// -> the 4 og-lanes of a warp read 4 distinct consecutive float4s (conflict-free LDS)
__global__ void prep_w(const float* __restrict__ w1,
                       float* __restrict__ wa, float* __restrict__ wc)
{
    int idx = blockIdx.x * 256 + threadIdx.x;
    if (idx >= CHC*9*CHC) return;
    int o = idx % CHC;
    int k = (idx / CHC) % 9;
    int c = idx / (CHC*9);
    int og = o >> 4, j = (o >> 2) & 3, m = o & 3;
    int p = ((j*4 + og) << 2) | m;
    wa[(c*9 + k)*64 + p] = w1[o*1152 + c*9 + k];
    wc[(c*9 + k)*64 + p] = w1[o*1152 + 576 + c*9 + k];
}

// ---------------- dual 3x3 conv, NHWC, zero-pad, 64->64 ----------------
// block: 256 threads = 64 quads(2x2 px) x 4 o-groups(16 o). tile 16x16. 8 c-chunks of 8.
__global__ __launch_bounds__(256, 2) void conv3x3_dual(
    const float4* __restrict__ inA, const float4* __restrict__ wA, float4* __restrict__ outA,
    const float4* __restrict__ inB, const float4* __restrict__ wB, float4* __restrict__ outB)
{
    __shared__ float4 s_in[2][18*18];   // [c-float4-within-chunk][y*18+x]
    __shared__ float4 s_w[8*9*16];      // [c-local][k][16 float4, swizzled over o]

    int which = blockIdx.z >> 2;
    int b = blockIdx.z & 3;
    const float4* in4 = which ? inB : inA;
    const float4* w4g = which ? wB : wA;
    float4* out4 = which ? outB : outA;

    int tid = threadIdx.x;
    int og = tid & 3;
    int q = tid >> 2;
    int qx = q & 7, qy = q >> 3;
    int tx0 = blockIdx.x * 16, ty0 = blockIdx.y * 16;

    float acc[4][16];
#pragma unroll
    for (int p = 0; p < 4; ++p)
#pragma unroll
        for (int j = 0; j < 16; ++j) acc[p][j] = 0.f;

    for (int cc = 0; cc < 8; ++cc) {
        __syncthreads();
        // input tile with halo: 18x18 x (2 float4) = 648 float4
        for (int i = tid; i < 648; i += 256) {
            int c2 = i / 324;
            int p = i - c2*324;
            int yy = p / 18;
            int xx = p - yy*18;
            int gy = ty0 + yy - 1, gx = tx0 + xx - 1;
            float4 v = make_float4(0.f, 0.f, 0.f, 0.f);
            if (gy >= 0 && gy < HH && gx >= 0 && gx < WW)
                v = in4[((b*HH + gy)*WW + gx)*16 + cc*2 + c2];
            s_in[c2][p] = v;
        }
        // weight chunk: 8c x 9k x 16 float4 = 1152 float4 (contiguous)
        for (int i = tid; i < 1152; i += 256)
            s_w[i] = w4g[cc*1152 + i];
        __syncthreads();

#pragma unroll
        for (int c2 = 0; c2 < 2; ++c2) {
#pragma unroll
            for (int k = 0; k < 9; ++k) {
                int kdy = k/3, kdx = k - kdy*3;
                int ri = (qy*2 + kdy)*18 + qx*2 + kdx;
                float4 v00 = s_in[c2][ri];
                float4 v01 = s_in[c2][ri + 1];
                float4 v10 = s_in[c2][ri + 18];
                float4 v11 = s_in[c2][ri + 19];
                float a0[4] = {v00.x, v00.y, v00.z, v00.w};
                float a1[4] = {v01.x, v01.y, v01.z, v01.w};
                float a2[4] = {v10.x, v10.y, v10.z, v10.w};
                float a3[4] = {v11.x, v11.y, v11.z, v11.w};
#pragma unroll
                for (int cc2 = 0; cc2 < 4; ++cc2) {
                    const float4* wp = &s_w[((c2*4 + cc2)*9 + k)*16 + og];
#pragma unroll
                    for (int j = 0; j < 4; ++j) {
                        float4 wv = wp[j*4];
                        acc[0][j*4+0] += a0[cc2]*wv.x; acc[0][j*4+1] += a0[cc2]*wv.y;
                        acc[0][j*4+2] += a0[cc2]*wv.z; acc[0][j*4+3] += a0[cc2]*wv.w;
                        acc[1][j*4+0] += a1[cc2]*wv.x; acc[1][j*4+1] += a1[cc2]*wv.y;
                        acc[1][j*4+2] += a1[cc2]*wv.z; acc[1][j*4+3] += a1[cc2]*wv.w;
                        acc[2][j*4+0] += a2[cc2]*wv.x; acc[2][j*4+1] += a2[cc2]*wv.y;
                        acc[2][j*4+2] += a2[cc2]*wv.z; acc[2][j*4+3] += a2[cc2]*wv.w;
                        acc[3][j*4+0] += a3[cc2]*wv.x; acc[3][j*4+1] += a3[cc2]*wv.y;
                        acc[3][j*4+2] += a3[cc2]*wv.z; acc[3][j*4+3] += a3[cc2]*wv.w;
                    }
                }
            }
        }
    }
    // store: channel float4 index = og*4 + j (matches swizzle o = og*16+j*4+m)
#pragma unroll
    for (int py = 0; py < 2; ++py)
#pragma unroll
        for (int px = 0; px < 2; ++px) {
            int p = py*2 + px;
            int gy = ty0 + qy*2 + py, gx = tx0 + qx*2 + px;
            int base = ((b*HH + gy)*WW + gx)*16 + og*4;
#pragma unroll
            for (int j = 0; j < 4; ++j)
                out4[base + j] = make_float4(acc[p][j*4+0], acc[p][j*4+1],
                                             acc[p][j*4+2], acc[p][j*4+3]);
        }
}

// ---------------- fused: bilinear(g) + cT + b1 -> leaky -> w2 -> softmax -> gather ----------------
// one warp per pixel, lane handles channels (2*lane, 2*lane+1)
__global__ __launch_bounds__(256) void fused_attn(
    const float* __restrict__ gT, const float* __restrict__ cT,
    const float* __restrict__ nbhT, const float* __restrict__ mv,
    const float* __restrict__ b1, const float* __restrict__ w2,
    const float* __restrict__ b2, float* __restrict__ outT)
{
    int gwarp = (blockIdx.x << 3) + (threadIdx.x >> 5);
    int lane = threadIdx.x & 31;
    int b = gwarp >> 14;
    int pix = gwarp & (HWS - 1);
    int y = pix >> 7, x = pix & 127;

    float mvx = mv[(b*2 + 0)*HWS + pix];
    float mvy = mv[(b*2 + 1)*HWS + pix];
    const float inv = 2.0f / 127.0f;
    float gx = fminf(fmaxf(-1.0f + inv*(float)x + mvx*0.5f, -1.0f), 1.0f);
    float gy = fminf(fmaxf(-1.0f + inv*(float)y + mvy*0.5f, -1.0f), 1.0f);
    float px = (gx + 1.0f) * 0.5f * 127.0f;
    float py = (gy + 1.0f) * 0.5f * 127.0f;
    float fx0 = floorf(px), fy0 = floorf(py);
    float wx = px - fx0, wy = py - fy0;
    int ix0 = min(max((int)fx0, 0), WW - 1);
    int iy0 = min(max((int)fy0, 0), HH - 1);
    int ix1 = min(ix0 + 1, WW - 1);
    int iy1 = min(iy0 + 1, HH - 1);

    const float2* g2 = (const float2*)gT;
    int pbase = b * HWS;
    float2 g00 = g2[(pbase + iy0*WW + ix0)*32 + lane];
    float2 g01 = g2[(pbase + iy0*WW + ix1)*32 + lane];
    float2 g10 = g2[(pbase + iy1*WW + ix0)*32 + lane];
    float2 g11 = g2[(pbase + iy1*WW + ix1)*32 + lane];
    float w00 = (1.f-wx)*(1.f-wy), w01 = wx*(1.f-wy), w10 = (1.f-wx)*wy, w11 = wx*wy;
    float2 cv = ((const float2*)cT)[(pbase + pix)*32 + lane];
    int c0 = lane*2;
    float h1a = g00.x*w00 + g01.x*w01 + g10.x*w10 + g11.x*w11 + cv.x + b1[c0];
    float h1b = g00.y*w00 + g01.y*w01 + g10.y*w10 + g11.y*w11 + cv.y + b1[c0+1];
    h1a = h1a >= 0.f ? h1a : 0.1f*h1a;
    h1b = h1b >= 0.f ? h1b : 0.1f*h1b;

    float part[9];
#pragma unroll
    for (int j = 0; j < 9; ++j)
        part[j] = w2[j*64 + c0]*h1a + w2[j*64 + c0 + 1]*h1b;
#pragma unroll
    for (int off = 16; off > 0; off >>= 1)
#pragma unroll
        for (int j = 0; j < 9; ++j)
            part[j] += __shfl_xor_sync(0xffffffffu, part[j], off);

    float mx = -1e30f;
#pragma unroll
    for (int j = 0; j < 9; ++j) { part[j] += b2[j]; mx = fmaxf(mx, part[j]); }
    float s = 0.f;
    float attn[9];
#pragma unroll
    for (int j = 0; j < 9; ++j) { attn[j] = __expf(part[j] - mx); s += attn[j]; }
    float sc = 1.0f / (9.0f * s);   // includes the mean over K2=9
#pragma unroll
    for (int j = 0; j < 9; ++j) attn[j] *= sc;

    // collapse (4 corners x 9 taps) -> 4x4 coefficient window, static indices only
    float wyv[2] = {1.f - wy, wy};
    float wxv[2] = {1.f - wx, wx};
    int d1y = iy1 - iy0;            // 0 at bottom border, else 1
    int d1x = ix1 - ix0;
    float Wrow[3][4], Wcol[3][4];
#pragma unroll
    for (int dy = 0; dy < 3; ++dy) {
#pragma unroll
        for (int r = 0; r < 4; ++r) { Wrow[dy][r] = 0.f; Wcol[dy][r] = 0.f; }
    }
#pragma unroll
    for (int dy = 0; dy < 3; ++dy) {
        int rowlo = iy0 + dy - 1;
        float vlo = (rowlo >= 0 && rowlo < HH) ? wyv[0] : 0.f;
        Wrow[dy][dy] += vlo;
        int rowhi = iy1 + dy - 1;
        float vhi = (rowhi >= 0 && rowhi < HH) ? wyv[1] : 0.f;
        if (d1y) Wrow[dy][dy+1] += vhi; else Wrow[dy][dy] += vhi;

        int collo = ix0 + dy - 1;
        float ulo = (collo >= 0 && collo < WW) ? wxv[0] : 0.f;
        Wcol[dy][dy] += ulo;
        int colhi = ix1 + dy - 1;
        float uhi = (colhi >= 0 && colhi < WW) ? wxv[1] : 0.f;
        if (d1x) Wcol[dy][dy+1] += uhi; else Wcol[dy][dy] += uhi;
    }
    float tmp[3][4];
#pragma unroll
    for (int dy = 0; dy < 3; ++dy)
#pragma unroll
        for (int sx = 0; sx < 4; ++sx) {
            float t = 0.f;
#pragma unroll
            for (int dx = 0; dx < 3; ++dx) t += attn[dy*3 + dx] * Wcol[dx][sx];
            tmp[dy][sx] = t;
        }
    float coeff[16];
#pragma unroll
    for (int r = 0; r < 4; ++r)
#pragma unroll
        for (int sx = 0; sx < 4; ++sx) {
            float t = 0.f;
#pragma unroll
            for (int dy = 0; dy < 3; ++dy) t += Wrow[dy][r] * tmp[dy][sx];
            coeff[r*4 + sx] = t;
        }

    const float2* n2 = (const float2*)nbhT;
    float oa = 0.f, ob = 0.f;
#pragma unroll
    for (int r = 0; r < 4; ++r) {
        int row = iy0 - 1 + r;
#pragma unroll
        for (int sx = 0; sx < 4; ++sx) {
            float cf = coeff[r*4 + sx];
            if (cf != 0.f) {            // exact zero for any OOB position -> load is safe
                int col = ix0 - 1 + sx;
                float2 v = n2[(pbase + row*WW + col)*32 + lane];
                oa += cf * v.x;
                ob += cf * v.y;
            }
        }
    }
    ((float2*)outT)[(pbase + pix)*32 + lane] = make_float2(oa, ob);
}

// ---------------- launcher ----------------
extern "C" void kernel_launch(void* const* d_in, const int* in_sizes, int n_in,
                              void* d_out, int out_size)
{
    const float* nbh = (const float*)d_in[0];
    const float* cen = (const float*)d_in[1];
    const float* mv  = (const float*)d_in[2];
    const float* w1  = (const float*)d_in[3];
    const float* b1  = (const float*)d_in[4];
    const float* w2  = (const float*)d_in[5];
    const float* b2  = (const float*)d_in[6];
    float* out = (float*)d_out;

    float *nbhT, *cenT, *gT, *cT, *outT, *w1a, *w1c;
    cudaGetSymbolAddress((void**)&nbhT, d_nbhT);
    cudaGetSymbolAddress((void**)&cenT, d_cenT);
    cudaGetSymbolAddress((void**)&gT,   d_gT);
    cudaGetSymbolAddress((void**)&cT,   d_cT);
    cudaGetSymbolAddress((void**)&outT, d_outT);
    cudaGetSymbolAddress((void**)&w1a,  d_w1a);
    cudaGetSymbolAddress((void**)&w1c,  d_w1c);

    prep_w<<<(CHC*9*CHC + 255)/256, 256>>>(w1, w1a, w1c);

    // NCHW -> NHWC (R=64 channels, C=HW)
    transpose_k<<<dim3(HWS/32, CHC/32, BB), dim3(32, 8)>>>(nbh, nbhT, CHC, HWS);
    transpose_k<<<dim3(HWS/32, CHC/32, BB), dim3(32, 8)>>>(cen, cenT, CHC, HWS);

    // both convs in one launch: grid.z = which*4 + b
    conv3x3_dual<<<dim3(8, 8, 8), 256>>>(
        (const float4*)nbhT, (const float4*)w1a, (float4*)gT,
        (const float4*)cenT, (const float4*)w1c, (float4*)cT);

    fused_attn<<<BB*HWS/8, 256>>>(gT, cT, nbhT, mv, b1, w2, b2, outT);

    // NHWC -> NCHW (input R=HW, C=64)
    transpose_k<<<dim3(CHC/32, HWS/32, BB), dim3(32, 8)>>>(outT, out, HWS, CHC);
}

// round 3
// speedup vs baseline: 2.3121x; 2.3121x over previous
#include <cuda_runtime.h>
#include <cuda_bf16.h>
#include <cstdint>

#define BB 4
#define CHC 64
#define HH 128
#define WW 128
#define HWS (HH*WW)

// ---------------- scratch (no allocations allowed) ----------------
__device__ __align__(256) float d_nbhT[BB*HWS*CHC];                 // NHWC nbh fp32
__device__ __align__(256) __nv_bfloat16 d_nbh_hl[BB*HWS*128];       // NHWC [hi64|lo64]
__device__ __align__(256) __nv_bfloat16 d_cen_hl[BB*HWS*128];
__device__ __align__(256) float d_gT[BB*HWS*CHC];                   // conv(nbh) NHWC fp32
__device__ __align__(256) float d_cT[BB*HWS*CHC];                   // conv(cen) NHWC fp32
__device__ __align__(256) float d_outT[BB*HWS*CHC];
__device__ __align__(256) __nv_bfloat16 d_wcomb[2*9*CHC*128];       // [conv][tap][o][hi64|lo64]

// ---------------- PTX helpers (portable sm_80+ subset only) ----------------
__device__ __forceinline__ uint32_t smem_u32(const void* p) {
    uint32_t a;
    asm("{ .reg .u64 t; cvta.to.shared.u64 t, %1; cvt.u32.u64 %0, t; }" : "=r"(a) : "l"(p));
    return a;
}
__device__ __forceinline__ void cpa16(uint32_t dst, const void* src) {
    asm volatile("cp.async.cg.shared.global [%0], [%1], 16;" :: "r"(dst), "l"(src));
}
__device__ __forceinline__ void ldsm4(uint32_t* r, uint32_t addr) {
    asm volatile("ldmatrix.sync.aligned.m8n8.x4.shared.b16 {%0,%1,%2,%3}, [%4];"
        : "=r"(r[0]), "=r"(r[1]), "=r"(r[2]), "=r"(r[3]) : "r"(addr));
}
__device__ __forceinline__ void mma_bf16(float* d, const uint32_t* a, const uint32_t* b) {
    asm volatile("mma.sync.aligned.m16n8k16.row.col.f32.bf16.bf16.f32 "
        "{%0,%1,%2,%3}, {%4,%5,%6,%7}, {%8,%9}, {%0,%1,%2,%3};"
        : "+f"(d[0]), "+f"(d[1]), "+f"(d[2]), "+f"(d[3])
        : "r"(a[0]), "r"(a[1]), "r"(a[2]), "r"(a[3]), "r"(b[0]), "r"(b[1]));
}

// ---------------- transpose NCHW->NHWC (+ optional bf16 hi/lo split) ----------------
__global__ void transpose_split(const float* __restrict__ in, float* __restrict__ out,
                                __nv_bfloat16* __restrict__ ohl, int R, int C)
{
    __shared__ float tile[32][33];
    int b = blockIdx.z;
    const float* inb = in + (size_t)b * R * C;
    size_t bo = (size_t)b * R * C;
    int c0 = blockIdx.x * 32;
    int r0 = blockIdx.y * 32;
#pragma unroll
    for (int i = 0; i < 32; i += 8)
        tile[threadIdx.y + i][threadIdx.x] =
            inb[(size_t)(r0 + threadIdx.y + i) * C + (c0 + threadIdx.x)];
    __syncthreads();
#pragma unroll
    for (int i = 0; i < 32; i += 8) {
        float v = tile[threadIdx.x][threadIdx.y + i];
        int px = c0 + threadIdx.y + i;
        int ch = r0 + threadIdx.x;
        if (out) out[bo + (size_t)px * 64 + ch] = v;
        __nv_bfloat16 h = __float2bfloat16(v);
        size_t hb = ((size_t)b * HWS + px) * 128 + ch;
        ohl[hb]      = h;
        ohl[hb + 64] = __float2bfloat16(v - __bfloat162float(h));
    }
}

// plain transpose (output NHWC -> NCHW)
__global__ void transpose_k(const float* __restrict__ in, float* __restrict__ out,
                            int R, int C)
{
    __shared__ float tile[32][33];
    int b = blockIdx.z;
    const float* inb = in + (size_t)b * R * C;
    float* outb = out + (size_t)b * R * C;
    int c0 = blockIdx.x * 32;
    int r0 = blockIdx.y * 32;
#pragma unroll
    for (int i = 0; i < 32; i += 8)
        tile[threadIdx.y + i][threadIdx.x] =
            inb[(size_t)(r0 + threadIdx.y + i) * C + (c0 + threadIdx.x)];
    __syncthreads();
#pragma unroll
    for (int i = 0; i < 32; i += 8)
        outb[(size_t)(c0 + threadIdx.y + i) * R + (r0 + threadIdx.x)] =
            tile[threadIdx.x][threadIdx.y + i];
}

// ---------------- weight prep: [conv][tap][o][hi64|lo64] bf16 ----------------
__global__ void prep_w(const float* __restrict__ w1, __nv_bfloat16* __restrict__ wcomb)
{
    int idx = blockIdx.x * 256 + threadIdx.x;   // 2*9*64*64 threads
    int c = idx & 63;
    int o = (idx >> 6) & 63;
    int tap = (idx >> 12) % 9;
    int conv = idx / (9 * 4096);
    float v = w1[o * 1152 + conv * 576 + c * 9 + tap];
    __nv_bfloat16 h = __float2bfloat16(v);
    size_t base = ((size_t)(conv * 9 + tap) * 64 + o) * 128;
    wcomb[base + c]      = h;
    wcomb[base + 64 + c] = __float2bfloat16(v - __bfloat162float(h));
}

// ---------------- HMMA dual conv3x3 ----------------
// CTA: (2-row tile, batch, conv). M=256 px (4x2 warp grid, warp M64xN32), N=64.
// Per tap: K=64 channels x 3 bf16 passes (hi*hi, hi*lo, lo*hi).
// smem: A halo 4 rows x 130 px x 256B (hi|lo) = 133120 B; W double buffer 2x16384 B.
#define A_BYTES (520*256)
#define W_OFF   A_BYTES
#define W_BYTES 16384
#define CONV_SMEM (A_BYTES + 2*W_BYTES)

__global__ void __launch_bounds__(256, 1) conv_tc(
    const __nv_bfloat16* __restrict__ nbh_hl,
    const __nv_bfloat16* __restrict__ cen_hl,
    const __nv_bfloat16* __restrict__ wcomb,
    float* __restrict__ gT, float* __restrict__ cT)
{
    extern __shared__ char smem[];
    const int tid = threadIdx.x;
    const int lane = tid & 31;
    const int wid = tid >> 5;
    const int mwarp = wid >> 1, nwarp = wid & 1;
    const int y0 = blockIdx.x * 2;
    const int b = blockIdx.y;
    const int conv = blockIdx.z;
    const __nv_bfloat16* src = conv ? cen_hl : nbh_hl;
    float* outp = conv ? cT : gT;
    const __nv_bfloat16* wsrc = wcomb + (size_t)conv * 9 * 64 * 128;
    const uint32_t sb = smem_u32(smem);

    // ---- stage A: 512 px x 16 chunks of 16B, swizzled; OOB rows -> zeros ----
#pragma unroll
    for (int it = 0; it < 32; ++it) {
        int i = tid + it * 256;
        int px = i >> 4, ch = i & 15;
        int ry = px >> 7, x = px & 127;
        int yy = y0 - 1 + ry;
        int pxb = ry * 130 + x + 1;
        uint32_t off = (uint32_t)pxb * 256 + (((uint32_t)ch ^ (pxb & 7)) << 4);
        if ((unsigned)yy < 128u)
            cpa16(sb + off, src + (((size_t)((b * 128 + yy) * 128 + x)) << 7) + ch * 8);
        else
            *(uint4*)(smem + off) = make_uint4(0u, 0u, 0u, 0u);
    }
    // pad columns x=-1 and x=128 (pxb x index 0 and 129), 4 halo rows
    if (tid < 128) {
        int pp = tid >> 4;
        int ry = pp >> 1;
        int xpad = (pp & 1) ? 129 : 0;
        int pxb = ry * 130 + xpad;
        int ch = tid & 15;
        uint32_t off = (uint32_t)pxb * 256 + (((uint32_t)ch ^ (pxb & 7)) << 4);
        *(uint4*)(smem + off) = make_uint4(0u, 0u, 0u, 0u);
    }
    // ---- stage W tap 0 ----
    {
        const __nv_bfloat16* w = wsrc;
        uint32_t base = sb + W_OFF;
#pragma unroll
        for (int it = 0; it < 4; ++it) {
            int i = tid + it * 256;
            int o = i >> 4, ch = i & 15;
            cpa16(base + (uint32_t)o * 256 + (((uint32_t)ch ^ (o & 7)) << 4), w + o * 128 + ch * 8);
        }
    }
    asm volatile("cp.async.commit_group;");
    asm volatile("cp.async.wait_group 0;");
    __syncthreads();

    float acc[4][4][4];
#pragma unroll
    for (int mt = 0; mt < 4; ++mt)
#pragma unroll
        for (int nt = 0; nt < 4; ++nt)
#pragma unroll
            for (int q = 0; q < 4; ++q) acc[mt][nt][q] = 0.f;

    const int chalfA = lane >> 4;         // A k-chunk half (which 8 channels of 16)
    const int chalfB = (lane >> 3) & 1;   // B k-chunk half
    const int o_ld = nwarp * 32 + (lane & 7) + ((lane >> 4) << 3);
    const uint32_t bsw = ((uint32_t)(o_ld & 7)) << 4;

    for (int t = 0; t < 9; ++t) {
        if (t < 8) {   // prefetch next tap weights into the other buffer
            const __nv_bfloat16* w = wsrc + (size_t)(t + 1) * 64 * 128;
            uint32_t base = sb + W_OFF + ((t + 1) & 1) * W_BYTES;
#pragma unroll
            for (int it = 0; it < 4; ++it) {
                int i = tid + it * 256;
                int o = i >> 4, ch = i & 15;
                cpa16(base + (uint32_t)o * 256 + (((uint32_t)ch ^ (o & 7)) << 4), w + o * 128 + ch * 8);
            }
            asm volatile("cp.async.commit_group;");
        }
        const int dy = t / 3 - 1, dx = t % 3 - 1;
        uint32_t arow[4], asw[4];
#pragma unroll
        for (int mt = 0; mt < 4; ++mt) {
            int m = mwarp * 64 + mt * 16 + (lane & 15);
            int r = m >> 7, x = m & 127;
            int pxb = (r + dy + 1) * 130 + (x + dx + 1);
            arow[mt] = sb + (uint32_t)pxb * 256;
            asw[mt] = ((uint32_t)(pxb & 7)) << 4;
        }
        const uint32_t wbase = sb + W_OFF + (t & 1) * W_BYTES;
        const uint32_t brow0 = wbase + (uint32_t)o_ld * 256;
        const uint32_t brow1 = brow0 + 16 * 256;

#pragma unroll
        for (int ks = 0; ks < 4; ++ks) {
            const uint32_t chi = (uint32_t)(ks * 2 + chalfA) << 4;
            uint32_t ahi[4][4], alo[4][4];
#pragma unroll
            for (int mt = 0; mt < 4; ++mt) {
                ldsm4(ahi[mt], arow[mt] + (chi ^ asw[mt]));
                ldsm4(alo[mt], arow[mt] + ((chi + 128) ^ asw[mt]));
            }
            const uint32_t cbi = (uint32_t)(ks * 2 + chalfB) << 4;
            uint32_t bhi[2][4], blo[2][4];
            ldsm4(bhi[0], brow0 + (cbi ^ bsw));
            ldsm4(bhi[1], brow1 + (cbi ^ bsw));
            ldsm4(blo[0], brow0 + ((cbi + 128) ^ bsw));
            ldsm4(blo[1], brow1 + ((cbi + 128) ^ bsw));
#pragma unroll
            for (int mt = 0; mt < 4; ++mt)
#pragma unroll
                for (int nt = 0; nt < 4; ++nt) {
                    int h = nt >> 1, s = (nt & 1) * 2;
                    mma_bf16(acc[mt][nt], ahi[mt], &bhi[h][s]);
                    mma_bf16(acc[mt][nt], ahi[mt], &blo[h][s]);
                    mma_bf16(acc[mt][nt], alo[mt], &bhi[h][s]);
                }
        }
        if (t < 8) {
            asm volatile("cp.async.wait_group 0;");
            __syncthreads();
        }
    }

    // ---- epilogue: fragments -> NHWC fp32 ----
#pragma unroll
    for (int mt = 0; mt < 4; ++mt) {
        int m0 = mwarp * 64 + mt * 16 + (lane >> 2);
#pragma unroll
        for (int half = 0; half < 2; ++half) {
            int m = m0 + half * 8;
            int y = y0 + (m >> 7), x = m & 127;
            float* rowp = outp + (((size_t)((b * 128 + y) * 128 + x)) << 6);
#pragma unroll
            for (int nt = 0; nt < 4; ++nt) {
                int o = nwarp * 32 + nt * 8 + (lane & 3) * 2;
                *(float2*)(rowp + o) = make_float2(acc[mt][nt][half * 2], acc[mt][nt][half * 2 + 1]);
            }
        }
    }
}

// ---------------- fused: bilinear(g) + cT + b1 -> leaky -> w2 -> softmax -> gather ----------------
__global__ void __launch_bounds__(256) fused_attn(
    const float* __restrict__ gT, const float* __restrict__ cT,
    const float* __restrict__ nbhT, const float* __restrict__ mv,
    const float* __restrict__ b1, const float* __restrict__ w2,
    const float* __restrict__ b2, float* __restrict__ outT)
{
    int gwarp = (blockIdx.x << 3) + (threadIdx.x >> 5);
    int lane = threadIdx.x & 31;
    int b = gwarp >> 14;
    int pix = gwarp & (HWS - 1);
    int y = pix >> 7, x = pix & 127;

    float mvx = mv[(b*2 + 0)*HWS + pix];
    float mvy = mv[(b*2 + 1)*HWS + pix];
    const float inv = 2.0f / 127.0f;
    float gx = fminf(fmaxf(-1.0f + inv*(float)x + mvx*0.5f, -1.0f), 1.0f);
    float gy = fminf(fmaxf(-1.0f + inv*(float)y + mvy*0.5f, -1.0f), 1.0f);
    float px = (gx + 1.0f) * 0.5f * 127.0f;
    float py = (gy + 1.0f) * 0.5f * 127.0f;
    float fx0 = floorf(px), fy0 = floorf(py);
    float wx = px - fx0, wy = py - fy0;
    int ix0 = min(max((int)fx0, 0), WW - 1);
    int iy0 = min(max((int)fy0, 0), HH - 1);
    int ix1 = min(ix0 + 1, WW - 1);
    int iy1 = min(iy0 + 1, HH - 1);

    const float2* g2 = (const float2*)gT;
    int pbase = b * HWS;
    float2 g00 = g2[(pbase + iy0*WW + ix0)*32 + lane];
    float2 g01 = g2[(pbase + iy0*WW + ix1)*32 + lane];
    float2 g10 = g2[(pbase + iy1*WW + ix0)*32 + lane];
    float2 g11 = g2[(pbase + iy1*WW + ix1)*32 + lane];
    float w00 = (1.f-wx)*(1.f-wy), w01 = wx*(1.f-wy), w10 = (1.f-wx)*wy, w11 = wx*wy;
    float2 cv = ((const float2*)cT)[(pbase + pix)*32 + lane];
    int c0 = lane*2;
    float h1a = g00.x*w00 + g01.x*w01 + g10.x*w10 + g11.x*w11 + cv.x + b1[c0];
    float h1b = g00.y*w00 + g01.y*w01 + g10.y*w10 + g11.y*w11 + cv.y + b1[c0+1];
    h1a = h1a >= 0.f ? h1a : 0.1f*h1a;
    h1b = h1b >= 0.f ? h1b : 0.1f*h1b;

    float part[9];
#pragma unroll
    for (int j = 0; j < 9; ++j)
        part[j] = w2[j*64 + c0]*h1a + w2[j*64 + c0 + 1]*h1b;
#pragma unroll
    for (int off = 16; off > 0; off >>= 1)
#pragma unroll
        for (int j = 0; j < 9; ++j)
            part[j] += __shfl_xor_sync(0xffffffffu, part[j], off);

    float mx = -1e30f;
#pragma unroll
    for (int j = 0; j < 9; ++j) { part[j] += b2[j]; mx = fmaxf(mx, part[j]); }
    float s = 0.f;
    float attn[9];
#pragma unroll
    for (int j = 0; j < 9; ++j) { attn[j] = __expf(part[j] - mx); s += attn[j]; }
    float sc = 1.0f / (9.0f * s);
#pragma unroll
    for (int j = 0; j < 9; ++j) attn[j] *= sc;

    float wyv[2] = {1.f - wy, wy};
    float wxv[2] = {1.f - wx, wx};
    int d1y = iy1 - iy0;
    int d1x = ix1 - ix0;
    float Wrow[3][4], Wcol[3][4];
#pragma unroll
    for (int dy = 0; dy < 3; ++dy)
#pragma unroll
        for (int r = 0; r < 4; ++r) { Wrow[dy][r] = 0.f; Wcol[dy][r] = 0.f; }
#pragma unroll
    for (int dy = 0; dy < 3; ++dy) {
        int rowlo = iy0 + dy - 1;
        float vlo = (rowlo >= 0 && rowlo < HH) ? wyv[0] : 0.f;
        Wrow[dy][dy] += vlo;
        int rowhi = iy1 + dy - 1;
        float vhi = (rowhi >= 0 && rowhi < HH) ? wyv[1] : 0.f;
        if (d1y) Wrow[dy][dy+1] += vhi; else Wrow[dy][dy] += vhi;

        int collo = ix0 + dy - 1;
        float ulo = (collo >= 0 && collo < WW) ? wxv[0] : 0.f;
        Wcol[dy][dy] += ulo;
        int colhi = ix1 + dy - 1;
        float uhi = (colhi >= 0 && colhi < WW) ? wxv[1] : 0.f;
        if (d1x) Wcol[dy][dy+1] += uhi; else Wcol[dy][dy] += uhi;
    }
    float tmp[3][4];
#pragma unroll
    for (int dy = 0; dy < 3; ++dy)
#pragma unroll
        for (int sx = 0; sx < 4; ++sx) {
            float t = 0.f;
#pragma unroll
            for (int dx = 0; dx < 3; ++dx) t += attn[dy*3 + dx] * Wcol[dx][sx];
            tmp[dy][sx] = t;
        }
    float coeff[16];
#pragma unroll
    for (int r = 0; r < 4; ++r)
#pragma unroll
        for (int sx = 0; sx < 4; ++sx) {
            float t = 0.f;
#pragma unroll
            for (int dy = 0; dy < 3; ++dy) t += Wrow[dy][r] * tmp[dy][sx];
            coeff[r*4 + sx] = t;
        }

    const float2* n2 = (const float2*)nbhT;
    float oa = 0.f, ob = 0.f;
#pragma unroll
    for (int r = 0; r < 4; ++r) {
        int row = iy0 - 1 + r;
#pragma unroll
        for (int sx = 0; sx < 4; ++sx) {
            float cf = coeff[r*4 + sx];
            if (cf != 0.f) {
                int col = ix0 - 1 + sx;
                float2 v = n2[(pbase + row*WW + col)*32 + lane];
                oa += cf * v.x;
                ob += cf * v.y;
            }
        }
    }
    ((float2*)outT)[(pbase + pix)*32 + lane] = make_float2(oa, ob);
}

// ---------------- launcher ----------------
extern "C" void kernel_launch(void* const* d_in, const int* in_sizes, int n_in,
                              void* d_out, int out_size)
{
    const float* nbh = (const float*)d_in[0];
    const float* cen = (const float*)d_in[1];
    const float* mv  = (const float*)d_in[2];
    const float* w1  = (const float*)d_in[3];
    const float* b1  = (const float*)d_in[4];
    const float* w2  = (const float*)d_in[5];
    const float* b2  = (const float*)d_in[6];
    float* out = (float*)d_out;

    float *nbhT, *gT, *cT, *outT;
    __nv_bfloat16 *nhl, *chl, *wc;
    cudaGetSymbolAddress((void**)&nbhT, d_nbhT);
    cudaGetSymbolAddress((void**)&gT,   d_gT);
    cudaGetSymbolAddress((void**)&cT,   d_cT);
    cudaGetSymbolAddress((void**)&outT, d_outT);
    cudaGetSymbolAddress((void**)&nhl,  d_nbh_hl);
    cudaGetSymbolAddress((void**)&chl,  d_cen_hl);
    cudaGetSymbolAddress((void**)&wc,   d_wcomb);

    cudaFuncSetAttribute(conv_tc, cudaFuncAttributeMaxDynamicSharedMemorySize, CONV_SMEM);

    prep_w<<<2*9*4096/256, 256>>>(w1, wc);

    // NCHW -> NHWC (+ hi/lo bf16 pack). cen needs no fp32 NHWC copy.
    transpose_split<<<dim3(HWS/32, CHC/32, BB), dim3(32, 8)>>>(nbh, nbhT, nhl, CHC, HWS);
    transpose_split<<<dim3(HWS/32, CHC/32, BB), dim3(32, 8)>>>(cen, (float*)nullptr, chl, CHC, HWS);

    // HMMA dual conv: grid (2-row tile, batch, conv)
    conv_tc<<<dim3(HH/2, BB, 2), 256, CONV_SMEM>>>(nhl, chl, wc, gT, cT);

    fused_attn<<<BB*HWS/8, 256>>>(gT, cT, nbhT, mv, b1, w2, b2, outT);

    // NHWC -> NCHW
    transpose_k<<<dim3(CHC/32, HWS/32, BB), dim3(32, 8)>>>(outT, out, HWS, CHC);
}

// round 4
// speedup vs baseline: 2.3126x; 1.0002x over previous
#include <cuda_runtime.h>
#include <cuda_bf16.h>
#include <cstdint>

#define BB 4
#define CHC 64
#define HH 128
#define WW 128
#define HWS (HH*WW)

// ---------------- scratch (no allocations allowed) ----------------
__device__ __align__(256) float d_nbhT[BB*HWS*CHC];                 // NHWC nbh fp32
__device__ __align__(256) __nv_bfloat16 d_nbh_hl[BB*HWS*128];       // NHWC [hi64|lo64]
__device__ __align__(256) __nv_bfloat16 d_cen_hl[BB*HWS*128];
__device__ __align__(256) float d_gT[BB*HWS*CHC];                   // conv(nbh) NHWC fp32
__device__ __align__(256) float d_cT[BB*HWS*CHC];                   // conv(cen) NHWC fp32
__device__ __align__(256) float d_outT[BB*HWS*CHC];
__device__ __align__(256) __nv_bfloat16 d_wcomb[2*9*CHC*128];       // [conv][tap][o][hi64|lo64]

// ---------------- PTX helpers (portable sm_80+ subset only) ----------------
__device__ __forceinline__ uint32_t smem_u32(const void* p) {
    uint32_t a;
    asm("{ .reg .u64 t; cvta.to.shared.u64 t, %1; cvt.u32.u64 %0, t; }" : "=r"(a) : "l"(p));
    return a;
}
__device__ __forceinline__ void cpa16(uint32_t dst, const void* src) {
    asm volatile("cp.async.cg.shared.global [%0], [%1], 16;" :: "r"(dst), "l"(src));
}
__device__ __forceinline__ void ldsm4(uint32_t* r, uint32_t addr) {
    asm volatile("ldmatrix.sync.aligned.m8n8.x4.shared.b16 {%0,%1,%2,%3}, [%4];"
        : "=r"(r[0]), "=r"(r[1]), "=r"(r[2]), "=r"(r[3]) : "r"(addr));
}
__device__ __forceinline__ void mma_bf16(float* d, const uint32_t* a, const uint32_t* b) {
    asm volatile("mma.sync.aligned.m16n8k16.row.col.f32.bf16.bf16.f32 "
        "{%0,%1,%2,%3}, {%4,%5,%6,%7}, {%8,%9}, {%0,%1,%2,%3};"
        : "+f"(d[0]), "+f"(d[1]), "+f"(d[2]), "+f"(d[3])
        : "r"(a[0]), "r"(a[1]), "r"(a[2]), "r"(a[3]), "r"(b[0]), "r"(b[1]));
}

// ---------------- transpose NCHW->NHWC for both inputs (+ bf16 hi/lo split) ----------------
// grid.z = which*4 + b. which==0: nbh (also writes fp32 NHWC); which==1: cen (bf16 only)
__global__ void transpose_split2(const float* __restrict__ nbh, const float* __restrict__ cen,
                                 float* __restrict__ outT, __nv_bfloat16* __restrict__ nhl,
                                 __nv_bfloat16* __restrict__ chl)
{
    __shared__ float tile[32][33];
    int which = blockIdx.z >> 2;
    int b = blockIdx.z & 3;
    const float* in = which ? cen : nbh;
    __nv_bfloat16* ohl = which ? chl : nhl;
    const float* inb = in + (size_t)b * CHC * HWS;
    int c0 = blockIdx.x * 32;   // pixel tile
    int r0 = blockIdx.y * 32;   // channel tile
#pragma unroll
    for (int i = 0; i < 32; i += 8)
        tile[threadIdx.y + i][threadIdx.x] =
            inb[(size_t)(r0 + threadIdx.y + i) * HWS + (c0 + threadIdx.x)];
    __syncthreads();
#pragma unroll
    for (int i = 0; i < 32; i += 8) {
        float v = tile[threadIdx.x][threadIdx.y + i];
        int px = c0 + threadIdx.y + i;
        int ch = r0 + threadIdx.x;
        if (!which) outT[((size_t)b * HWS + px) * 64 + ch] = v;
        __nv_bfloat16 h = __float2bfloat16(v);
        size_t hb = ((size_t)b * HWS + px) * 128 + ch;
        ohl[hb]      = h;
        ohl[hb + 64] = __float2bfloat16(v - __bfloat162float(h));
    }
}

// plain transpose (output NHWC -> NCHW)
__global__ void transpose_k(const float* __restrict__ in, float* __restrict__ out,
                            int R, int C)
{
    __shared__ float tile[32][33];
    int b = blockIdx.z;
    const float* inb = in + (size_t)b * R * C;
    float* outb = out + (size_t)b * R * C;
    int c0 = blockIdx.x * 32;
    int r0 = blockIdx.y * 32;
#pragma unroll
    for (int i = 0; i < 32; i += 8)
        tile[threadIdx.y + i][threadIdx.x] =
            inb[(size_t)(r0 + threadIdx.y + i) * C + (c0 + threadIdx.x)];
    __syncthreads();
#pragma unroll
    for (int i = 0; i < 32; i += 8)
        outb[(size_t)(c0 + threadIdx.y + i) * R + (r0 + threadIdx.x)] =
            tile[threadIdx.x][threadIdx.y + i];
}

// ---------------- weight prep: [conv][tap][o][hi64|lo64] bf16 ----------------
__global__ void prep_w(const float* __restrict__ w1, __nv_bfloat16* __restrict__ wcomb)
{
    int idx = blockIdx.x * 256 + threadIdx.x;   // 2*9*64*64 threads
    int c = idx & 63;
    int o = (idx >> 6) & 63;
    int tap = (idx >> 12) % 9;
    int conv = idx / (9 * 4096);
    float v = w1[o * 1152 + conv * 576 + c * 9 + tap];
    __nv_bfloat16 h = __float2bfloat16(v);
    size_t base = ((size_t)(conv * 9 + tap) * 64 + o) * 128;
    wcomb[base + c]      = h;
    wcomb[base + 64 + c] = __float2bfloat16(v - __bfloat162float(h));
}

// ---------------- HMMA dual conv3x3 (16 warps, warp tile M64xN16) ----------------
// CTA: (2-row tile, batch, conv). M=256 px, N=64. 4x4 warp grid.
// Per tap: K=64 channels x 3 bf16 passes (hi*hi, hi*lo, lo*hi).
// smem: A halo 4 rows x 130 px x 256B (hi|lo) = 133120 B; W double buffer 2x16384 B.
#define A_BYTES (520*256)
#define W_OFF   A_BYTES
#define W_BYTES 16384
#define CONV_SMEM (A_BYTES + 2*W_BYTES)

__global__ void __launch_bounds__(512, 1) conv_tc(
    const __nv_bfloat16* __restrict__ nbh_hl,
    const __nv_bfloat16* __restrict__ cen_hl,
    const __nv_bfloat16* __restrict__ wcomb,
    float* __restrict__ gT, float* __restrict__ cT)
{
    extern __shared__ char smem[];
    const int tid = threadIdx.x;
    const int lane = tid & 31;
    const int wid = tid >> 5;
    const int mwarp = wid >> 2, nwarp = wid & 3;
    const int y0 = blockIdx.x * 2;
    const int b = blockIdx.y;
    const int conv = blockIdx.z;
    const __nv_bfloat16* src = conv ? cen_hl : nbh_hl;
    float* outp = conv ? cT : gT;
    const __nv_bfloat16* wsrc = wcomb + (size_t)conv * 9 * 64 * 128;
    const uint32_t sb = smem_u32(smem);

    // ---- stage A: 512 px x 16 chunks of 16B, swizzled; OOB rows -> zeros ----
#pragma unroll
    for (int it = 0; it < 16; ++it) {
        int i = tid + it * 512;
        int px = i >> 4, ch = i & 15;
        int ry = px >> 7, x = px & 127;
        int yy = y0 - 1 + ry;
        int pxb = ry * 130 + x + 1;
        uint32_t off = (uint32_t)pxb * 256 + (((uint32_t)ch ^ (pxb & 7)) << 4);
        if ((unsigned)yy < 128u)
            cpa16(sb + off, src + (((size_t)((b * 128 + yy) * 128 + x)) << 7) + ch * 8);
        else
            *(uint4*)(smem + off) = make_uint4(0u, 0u, 0u, 0u);
    }
    // pad columns x=-1 and x=128 (pxb x index 0 and 129), 4 halo rows
    if (tid < 128) {
        int pp = tid >> 4;
        int ry = pp >> 1;
        int xpad = (pp & 1) ? 129 : 0;
        int pxb = ry * 130 + xpad;
        int ch = tid & 15;
        uint32_t off = (uint32_t)pxb * 256 + (((uint32_t)ch ^ (pxb & 7)) << 4);
        *(uint4*)(smem + off) = make_uint4(0u, 0u, 0u, 0u);
    }
    // ---- stage W tap 0 ----
    {
        const __nv_bfloat16* w = wsrc;
        uint32_t base = sb + W_OFF;
#pragma unroll
        for (int it = 0; it < 2; ++it) {
            int i = tid + it * 512;
            int o = i >> 4, ch = i & 15;
            cpa16(base + (uint32_t)o * 256 + (((uint32_t)ch ^ (o & 7)) << 4), w + o * 128 + ch * 8);
        }
    }
    asm volatile("cp.async.commit_group;");
    asm volatile("cp.async.wait_group 0;");
    __syncthreads();

    float acc[4][2][4];
#pragma unroll
    for (int mt = 0; mt < 4; ++mt)
#pragma unroll
        for (int nt = 0; nt < 2; ++nt)
#pragma unroll
            for (int q = 0; q < 4; ++q) acc[mt][nt][q] = 0.f;

    const int chalfA = lane >> 4;         // A k-chunk half (which 8 channels of 16)
    const int chalfB = (lane >> 3) & 1;   // B k-chunk half
    const int o_ld = nwarp * 16 + (lane & 7) + ((lane >> 4) << 3);
    const uint32_t bsw = ((uint32_t)(o_ld & 7)) << 4;

    for (int t = 0; t < 9; ++t) {
        if (t < 8) {   // prefetch next tap weights into the other buffer
            const __nv_bfloat16* w = wsrc + (size_t)(t + 1) * 64 * 128;
            uint32_t base = sb + W_OFF + ((t + 1) & 1) * W_BYTES;
#pragma unroll
            for (int it = 0; it < 2; ++it) {
                int i = tid + it * 512;
                int o = i >> 4, ch = i & 15;
                cpa16(base + (uint32_t)o * 256 + (((uint32_t)ch ^ (o & 7)) << 4), w + o * 128 + ch * 8);
            }
            asm volatile("cp.async.commit_group;");
        }
        const int dy = t / 3 - 1, dx = t % 3 - 1;
        uint32_t arow[4], asw[4];
#pragma unroll
        for (int mt = 0; mt < 4; ++mt) {
            int m = mwarp * 64 + mt * 16 + (lane & 15);
            int r = m >> 7, x = m & 127;
            int pxb = (r + dy + 1) * 130 + (x + dx + 1);
            arow[mt] = sb + (uint32_t)pxb * 256;
            asw[mt] = ((uint32_t)(pxb & 7)) << 4;
        }
        const uint32_t brow = sb + W_OFF + (t & 1) * W_BYTES + (uint32_t)o_ld * 256;

#pragma unroll
        for (int ks = 0; ks < 4; ++ks) {
            const uint32_t chi = (uint32_t)(ks * 2 + chalfA) << 4;
            uint32_t ahi[4][4], alo[4][4];
#pragma unroll
            for (int mt = 0; mt < 4; ++mt) {
                ldsm4(ahi[mt], arow[mt] + (chi ^ asw[mt]));
                ldsm4(alo[mt], arow[mt] + ((chi + 128) ^ asw[mt]));
            }
            const uint32_t cbi = (uint32_t)(ks * 2 + chalfB) << 4;
            uint32_t bhi[4], blo[4];
            ldsm4(bhi, brow + (cbi ^ bsw));
            ldsm4(blo, brow + ((cbi + 128) ^ bsw));
#pragma unroll
            for (int mt = 0; mt < 4; ++mt)
#pragma unroll
                for (int nt = 0; nt < 2; ++nt) {
                    mma_bf16(acc[mt][nt], ahi[mt], &bhi[nt * 2]);
                    mma_bf16(acc[mt][nt], ahi[mt], &blo[nt * 2]);
                    mma_bf16(acc[mt][nt], alo[mt], &bhi[nt * 2]);
                }
        }
        if (t < 8) {
            asm volatile("cp.async.wait_group 0;");
            __syncthreads();
        }
    }

    // ---- epilogue: fragments -> NHWC fp32 ----
#pragma unroll
    for (int mt = 0; mt < 4; ++mt) {
        int m0 = mwarp * 64 + mt * 16 + (lane >> 2);
#pragma unroll
        for (int half = 0; half < 2; ++half) {
            int m = m0 + half * 8;
            int y = y0 + (m >> 7), x = m & 127;
            float* rowp = outp + (((size_t)((b * 128 + y) * 128 + x)) << 6);
#pragma unroll
            for (int nt = 0; nt < 2; ++nt) {
                int o = nwarp * 16 + nt * 8 + (lane & 3) * 2;
                *(float2*)(rowp + o) = make_float2(acc[mt][nt][half * 2], acc[mt][nt][half * 2 + 1]);
            }
        }
    }
}

// ---------------- fused: bilinear(g) + cT + b1 -> leaky -> w2 -> softmax -> gather ----------------
__global__ void __launch_bounds__(256) fused_attn(
    const float* __restrict__ gT, const float* __restrict__ cT,
    const float* __restrict__ nbhT, const float* __restrict__ mv,
    const float* __restrict__ b1, const float* __restrict__ w2,
    const float* __restrict__ b2, float* __restrict__ outT)
{
    int gwarp = (blockIdx.x << 3) + (threadIdx.x >> 5);
    int lane = threadIdx.x & 31;
    int b = gwarp >> 14;
    int pix = gwarp & (HWS - 1);
    int y = pix >> 7, x = pix & 127;

    float mvx = mv[(b*2 + 0)*HWS + pix];
    float mvy = mv[(b*2 + 1)*HWS + pix];
    const float inv = 2.0f / 127.0f;
    float gx = fminf(fmaxf(-1.0f + inv*(float)x + mvx*0.5f, -1.0f), 1.0f);
    float gy = fminf(fmaxf(-1.0f + inv*(float)y + mvy*0.5f, -1.0f), 1.0f);
    float px = (gx + 1.0f) * 0.5f * 127.0f;
    float py = (gy + 1.0f) * 0.5f * 127.0f;
    float fx0 = floorf(px), fy0 = floorf(py);
    float wx = px - fx0, wy = py - fy0;
    int ix0 = min(max((int)fx0, 0), WW - 1);
    int iy0 = min(max((int)fy0, 0), HH - 1);
    int ix1 = min(ix0 + 1, WW - 1);
    int iy1 = min(iy0 + 1, HH - 1);

    const float2* g2 = (const float2*)gT;
    int pbase = b * HWS;
    float2 g00 = g2[(pbase + iy0*WW + ix0)*32 + lane];
    float2 g01 = g2[(pbase + iy0*WW + ix1)*32 + lane];
    float2 g10 = g2[(pbase + iy1*WW + ix0)*32 + lane];
    float2 g11 = g2[(pbase + iy1*WW + ix1)*32 + lane];
    float w00 = (1.f-wx)*(1.f-wy), w01 = wx*(1.f-wy), w10 = (1.f-wx)*wy, w11 = wx*wy;
    float2 cv = ((const float2*)cT)[(pbase + pix)*32 + lane];
    int c0 = lane*2;
    float h1a = g00.x*w00 + g01.x*w01 + g10.x*w10 + g11.x*w11 + cv.x + b1[c0];
    float h1b = g00.y*w00 + g01.y*w01 + g10.y*w10 + g11.y*w11 + cv.y + b1[c0+1];
    h1a = h1a >= 0.f ? h1a : 0.1f*h1a;
    h1b = h1b >= 0.f ? h1b : 0.1f*h1b;

    float part[9];
#pragma unroll
    for (int j = 0; j < 9; ++j)
        part[j] = w2[j*64 + c0]*h1a + w2[j*64 + c0 + 1]*h1b;
#pragma unroll
    for (int off = 16; off > 0; off >>= 1)
#pragma unroll
        for (int j = 0; j < 9; ++j)
            part[j] += __shfl_xor_sync(0xffffffffu, part[j], off);

    float mx = -1e30f;
#pragma unroll
    for (int j = 0; j < 9; ++j) { part[j] += b2[j]; mx = fmaxf(mx, part[j]); }
    float s = 0.f;
    float attn[9];
#pragma unroll
    for (int j = 0; j < 9; ++j) { attn[j] = __expf(part[j] - mx); s += attn[j]; }
    float sc = 1.0f / (9.0f * s);
#pragma unroll
    for (int j = 0; j < 9; ++j) attn[j] *= sc;

    float wyv[2] = {1.f - wy, wy};
    float wxv[2] = {1.f - wx, wx};
    int d1y = iy1 - iy0;
    int d1x = ix1 - ix0;
    float Wrow[3][4], Wcol[3][4];
#pragma unroll
    for (int dy = 0; dy < 3; ++dy)
#pragma unroll
        for (int r = 0; r < 4; ++r) { Wrow[dy][r] = 0.f; Wcol[dy][r] = 0.f; }
#pragma unroll
    for (int dy = 0; dy < 3; ++dy) {
        int rowlo = iy0 + dy - 1;
        float vlo = (rowlo >= 0 && rowlo < HH) ? wyv[0] : 0.f;
        Wrow[dy][dy] += vlo;
        int rowhi = iy1 + dy - 1;
        float vhi = (rowhi >= 0 && rowhi < HH) ? wyv[1] : 0.f;
        if (d1y) Wrow[dy][dy+1] += vhi; else Wrow[dy][dy] += vhi;

        int collo = ix0 + dy - 1;
        float ulo = (collo >= 0 && collo < WW) ? wxv[0] : 0.f;
        Wcol[dy][dy] += ulo;
        int colhi = ix1 + dy - 1;
        float uhi = (colhi >= 0 && colhi < WW) ? wxv[1] : 0.f;
        if (d1x) Wcol[dy][dy+1] += uhi; else Wcol[dy][dy] += uhi;
    }
    float tmp[3][4];
#pragma unroll
    for (int dy = 0; dy < 3; ++dy)
#pragma unroll
        for (int sx = 0; sx < 4; ++sx) {
            float t = 0.f;
#pragma unroll
            for (int dx = 0; dx < 3; ++dx) t += attn[dy*3 + dx] * Wcol[dx][sx];
            tmp[dy][sx] = t;
        }
    float coeff[16];
#pragma unroll
    for (int r = 0; r < 4; ++r)
#pragma unroll
        for (int sx = 0; sx < 4; ++sx) {
            float t = 0.f;
#pragma unroll
            for (int dy = 0; dy < 3; ++dy) t += Wrow[dy][r] * tmp[dy][sx];
            coeff[r*4 + sx] = t;
        }

    const float2* n2 = (const float2*)nbhT;
    float oa = 0.f, ob = 0.f;
#pragma unroll
    for (int r = 0; r < 4; ++r) {
        int row = iy0 - 1 + r;
#pragma unroll
        for (int sx = 0; sx < 4; ++sx) {
            float cf = coeff[r*4 + sx];
            if (cf != 0.f) {
                int col = ix0 - 1 + sx;
                float2 v = n2[(pbase + row*WW + col)*32 + lane];
                oa += cf * v.x;
                ob += cf * v.y;
            }
        }
    }
    ((float2*)outT)[(pbase + pix)*32 + lane] = make_float2(oa, ob);
}

// ---------------- launcher ----------------
extern "C" void kernel_launch(void* const* d_in, const int* in_sizes, int n_in,
                              void* d_out, int out_size)
{
    const float* nbh = (const float*)d_in[0];
    const float* cen = (const float*)d_in[1];
    const float* mv  = (const float*)d_in[2];
    const float* w1  = (const float*)d_in[3];
    const float* b1  = (const float*)d_in[4];
    const float* w2  = (const float*)d_in[5];
    const float* b2  = (const float*)d_in[6];
    float* out = (float*)d_out;

    float *nbhT, *gT, *cT, *outT;
    __nv_bfloat16 *nhl, *chl, *wc;
    cudaGetSymbolAddress((void**)&nbhT, d_nbhT);
    cudaGetSymbolAddress((void**)&gT,   d_gT);
    cudaGetSymbolAddress((void**)&cT,   d_cT);
    cudaGetSymbolAddress((void**)&outT, d_outT);
    cudaGetSymbolAddress((void**)&nhl,  d_nbh_hl);
    cudaGetSymbolAddress((void**)&chl,  d_cen_hl);
    cudaGetSymbolAddress((void**)&wc,   d_wcomb);

    cudaFuncSetAttribute(conv_tc, cudaFuncAttributeMaxDynamicSharedMemorySize, CONV_SMEM);

    prep_w<<<2*9*4096/256, 256>>>(w1, wc);

    // NCHW -> NHWC (+ hi/lo bf16 pack) for both inputs in one launch
    transpose_split2<<<dim3(HWS/32, CHC/32, 2*BB), dim3(32, 8)>>>(nbh, cen, nbhT, nhl, chl);

    // HMMA dual conv: grid (2-row tile, batch, conv)
    conv_tc<<<dim3(HH/2, BB, 2), 512, CONV_SMEM>>>(nhl, chl, wc, gT, cT);

    fused_attn<<<BB*HWS/8, 256>>>(gT, cT, nbhT, mv, b1, w2, b2, outT);

    // NHWC -> NCHW
    transpose_k<<<dim3(CHC/32, HWS/32, BB), dim3(32, 8)>>>(outT, out, HWS, CHC);
}

// round 5
// speedup vs baseline: 3.4086x; 1.4739x over previous
#include <cuda_runtime.h>
#include <cuda_fp16.h>
#include <cstdint>

#define BB 4
#define CHC 64
#define HH 128
#define WW 128
#define HWS (HH*WW)

// ---------------- scratch (no allocations allowed) ----------------
__device__ __align__(256) float d_nbhT[BB*HWS*CHC];        // NHWC nbh fp32
__device__ __align__(256) __half d_nbh_h[BB*HWS*CHC];      // NHWC fp16
__device__ __align__(256) __half d_cen_h[BB*HWS*CHC];
__device__ __align__(256) float d_gT[BB*HWS*CHC];          // conv(nbh) NHWC fp32
__device__ __align__(256) float d_cT[BB*HWS*CHC];          // conv(cen) NHWC fp32
__device__ __align__(256) float d_outT[BB*HWS*CHC];
__device__ __align__(256) __half d_wcomb[2*9*CHC*CHC];     // [conv][tap][o][c] fp16

// ---------------- PTX helpers (portable sm_80+ subset only) ----------------
__device__ __forceinline__ uint32_t smem_u32(const void* p) {
    uint32_t a;
    asm("{ .reg .u64 t; cvta.to.shared.u64 t, %1; cvt.u32.u64 %0, t; }" : "=r"(a) : "l"(p));
    return a;
}
__device__ __forceinline__ void cpa16(uint32_t dst, const void* src) {
    asm volatile("cp.async.cg.shared.global [%0], [%1], 16;" :: "r"(dst), "l"(src));
}
__device__ __forceinline__ void ldsm4(uint32_t* r, uint32_t addr) {
    asm volatile("ldmatrix.sync.aligned.m8n8.x4.shared.b16 {%0,%1,%2,%3}, [%4];"
        : "=r"(r[0]), "=r"(r[1]), "=r"(r[2]), "=r"(r[3]) : "r"(addr));
}
__device__ __forceinline__ void mma_fp16(float* d, const uint32_t* a, const uint32_t* b) {
    asm volatile("mma.sync.aligned.m16n8k16.row.col.f32.f16.f16.f32 "
        "{%0,%1,%2,%3}, {%4,%5,%6,%7}, {%8,%9}, {%0,%1,%2,%3};"
        : "+f"(d[0]), "+f"(d[1]), "+f"(d[2]), "+f"(d[3])
        : "r"(a[0]), "r"(a[1]), "r"(a[2]), "r"(a[3]), "r"(b[0]), "r"(b[1]));
}

// ---------------- transpose NCHW->NHWC for both inputs (+ fp16 cast) ----------------
// grid.z = which*4 + b. which==0: nbh (also writes fp32 NHWC); which==1: cen (fp16 only)
__global__ void transpose_split2(const float* __restrict__ nbh, const float* __restrict__ cen,
                                 float* __restrict__ outT, __half* __restrict__ nh,
                                 __half* __restrict__ ch)
{
    __shared__ float tile[32][33];
    int which = blockIdx.z >> 2;
    int b = blockIdx.z & 3;
    const float* in = which ? cen : nbh;
    __half* oh = which ? ch : nh;
    const float* inb = in + (size_t)b * CHC * HWS;
    int c0 = blockIdx.x * 32;   // pixel tile
    int r0 = blockIdx.y * 32;   // channel tile
#pragma unroll
    for (int i = 0; i < 32; i += 8)
        tile[threadIdx.y + i][threadIdx.x] =
            inb[(size_t)(r0 + threadIdx.y + i) * HWS + (c0 + threadIdx.x)];
    __syncthreads();
#pragma unroll
    for (int i = 0; i < 32; i += 8) {
        float v = tile[threadIdx.x][threadIdx.y + i];
        int px = c0 + threadIdx.y + i;
        int chn = r0 + threadIdx.x;
        size_t oi = ((size_t)b * HWS + px) * 64 + chn;
        if (!which) outT[oi] = v;
        oh[oi] = __float2half(v);
    }
}

// plain transpose (output NHWC -> NCHW)
__global__ void transpose_k(const float* __restrict__ in, float* __restrict__ out,
                            int R, int C)
{
    __shared__ float tile[32][33];
    int b = blockIdx.z;
    const float* inb = in + (size_t)b * R * C;
    float* outb = out + (size_t)b * R * C;
    int c0 = blockIdx.x * 32;
    int r0 = blockIdx.y * 32;
#pragma unroll
    for (int i = 0; i < 32; i += 8)
        tile[threadIdx.y + i][threadIdx.x] =
            inb[(size_t)(r0 + threadIdx.y + i) * C + (c0 + threadIdx.x)];
    __syncthreads();
#pragma unroll
    for (int i = 0; i < 32; i += 8)
        outb[(size_t)(c0 + threadIdx.y + i) * R + (r0 + threadIdx.x)] =
            tile[threadIdx.x][threadIdx.y + i];
}

// ---------------- weight prep: [conv][tap][o][c] fp16 ----------------
__global__ void prep_w(const float* __restrict__ w1, __half* __restrict__ wcomb)
{
    int idx = blockIdx.x * 256 + threadIdx.x;   // 2*9*64*64 threads
    int c = idx & 63;
    int o = (idx >> 6) & 63;
    int tap = (idx >> 12) % 9;
    int conv = idx / (9 * 4096);
    wcomb[idx] = __float2half(w1[o * 1152 + conv * 576 + c * 9 + tap]);
}

// ---------------- HMMA dual conv3x3, single-pass fp16 ----------------
// CTA: (2-row tile, batch, conv). M=256 px, N=64. 4x4 warp grid, warp tile M64xN16.
// smem: A halo 4 rows x 130 px x 128B = 66560 B; W all 9 taps: 576 rows x 128B = 73728 B.
#define A_BYTES (520*128)
#define W_OFF   A_BYTES
#define CONV_SMEM (A_BYTES + 9*64*128)

__global__ void __launch_bounds__(512, 1) conv_tc(
    const __half* __restrict__ nbh_h,
    const __half* __restrict__ cen_h,
    const __half* __restrict__ wcomb,
    float* __restrict__ gT, float* __restrict__ cT)
{
    extern __shared__ char smem[];
    const int tid = threadIdx.x;
    const int lane = tid & 31;
    const int wid = tid >> 5;
    const int mwarp = wid >> 2, nwarp = wid & 3;
    const int y0 = blockIdx.x * 2;
    const int b = blockIdx.y;
    const int conv = blockIdx.z;
    const __half* src = conv ? cen_h : nbh_h;
    float* outp = conv ? cT : gT;
    const __half* wsrc = wcomb + (size_t)conv * 9 * 4096;
    const uint32_t sb = smem_u32(smem);

    // ---- stage A: 512 px x 8 chunks of 16B, swizzled; OOB rows -> zeros ----
#pragma unroll
    for (int it = 0; it < 8; ++it) {
        int i = tid + it * 512;
        int px = i >> 3, chn = i & 7;
        int ry = px >> 7, x = px & 127;
        int yy = y0 - 1 + ry;
        int pxb = ry * 130 + x + 1;
        uint32_t off = (uint32_t)pxb * 128 + (((uint32_t)chn ^ (pxb & 7)) << 4);
        if ((unsigned)yy < 128u)
            cpa16(sb + off, src + (((size_t)((b * 128 + yy) * 128 + x)) << 6) + chn * 8);
        else
            *(uint4*)(smem + off) = make_uint4(0u, 0u, 0u, 0u);
    }
    // pad columns x=-1 and x=128 (pxb x index 0 and 129), 4 halo rows
    if (tid < 64) {
        int pp = tid >> 3;
        int ry = pp >> 1;
        int xpad = (pp & 1) ? 129 : 0;
        int pxb = ry * 130 + xpad;
        int chn = tid & 7;
        uint32_t off = (uint32_t)pxb * 128 + (((uint32_t)chn ^ (pxb & 7)) << 4);
        *(uint4*)(smem + off) = make_uint4(0u, 0u, 0u, 0u);
    }
    // ---- stage all 9 taps of W: 576 o-rows x 8 chunks ----
#pragma unroll
    for (int it = 0; it < 9; ++it) {
        int i = tid + it * 512;
        int row = i >> 3, chn = i & 7;
        uint32_t off = W_OFF + (uint32_t)row * 128 + (((uint32_t)chn ^ (row & 7)) << 4);
        cpa16(sb + off, wsrc + row * 64 + chn * 8);
    }
    asm volatile("cp.async.commit_group;");
    asm volatile("cp.async.wait_group 0;");
    __syncthreads();

    float acc[4][2][4];
#pragma unroll
    for (int mt = 0; mt < 4; ++mt)
#pragma unroll
        for (int nt = 0; nt < 2; ++nt)
#pragma unroll
            for (int q = 0; q < 4; ++q) acc[mt][nt][q] = 0.f;

    const int chalfA = lane >> 4;         // which 16B chunk of the k16 (channels 0-7 / 8-15)
    const int chalfB = (lane >> 3) & 1;
    const int o_ld = nwarp * 16 + (lane & 7) + ((lane >> 4) << 3);
    const uint32_t bsw = ((uint32_t)(o_ld & 7)) << 4;
    const uint32_t browb = sb + W_OFF + (uint32_t)o_ld * 128;

    // base px (m) coordinates for this warp's 4 m-tiles
    int mbase[4], mx[4];
#pragma unroll
    for (int mt = 0; mt < 4; ++mt) {
        int m = mwarp * 64 + mt * 16 + (lane & 15);
        mbase[mt] = (m >> 7);      // row within 2-row tile
        mx[mt] = m & 127;
    }

#pragma unroll
    for (int t = 0; t < 9; ++t) {
        const int dy = t / 3 - 1, dx = t % 3 - 1;
        uint32_t arow[4], asw[4];
#pragma unroll
        for (int mt = 0; mt < 4; ++mt) {
            int pxb = (mbase[mt] + dy + 1) * 130 + (mx[mt] + dx + 1);
            arow[mt] = sb + (uint32_t)pxb * 128;
            asw[mt] = ((uint32_t)(pxb & 7)) << 4;
        }
        const uint32_t brow = browb + (uint32_t)t * 64 * 128;

#pragma unroll
        for (int ks = 0; ks < 4; ++ks) {
            const uint32_t chi = (uint32_t)(ks * 2 + chalfA) << 4;
            uint32_t a[4][4];
#pragma unroll
            for (int mt = 0; mt < 4; ++mt)
                ldsm4(a[mt], arow[mt] + (chi ^ asw[mt]));
            const uint32_t cbi = (uint32_t)(ks * 2 + chalfB) << 4;
            uint32_t bv[4];
            ldsm4(bv, brow + (cbi ^ bsw));
#pragma unroll
            for (int mt = 0; mt < 4; ++mt)
#pragma unroll
                for (int nt = 0; nt < 2; ++nt)
                    mma_fp16(acc[mt][nt], a[mt], &bv[nt * 2]);
        }
    }

    // ---- epilogue: fragments -> NHWC fp32 ----
#pragma unroll
    for (int mt = 0; mt < 4; ++mt) {
        int m0 = mwarp * 64 + mt * 16 + (lane >> 2);
#pragma unroll
        for (int half = 0; half < 2; ++half) {
            int m = m0 + half * 8;
            int y = y0 + (m >> 7), x = m & 127;
            float* rowp = outp + (((size_t)((b * 128 + y) * 128 + x)) << 6);
#pragma unroll
            for (int nt = 0; nt < 2; ++nt) {
                int o = nwarp * 16 + nt * 8 + (lane & 3) * 2;
                *(float2*)(rowp + o) = make_float2(acc[mt][nt][half * 2], acc[mt][nt][half * 2 + 1]);
            }
        }
    }
}

// ---------------- fused: bilinear(g) + cT + b1 -> leaky -> w2 -> softmax -> gather ----------------
__global__ void __launch_bounds__(256) fused_attn(
    const float* __restrict__ gT, const float* __restrict__ cT,
    const float* __restrict__ nbhT, const float* __restrict__ mv,
    const float* __restrict__ b1, const float* __restrict__ w2,
    const float* __restrict__ b2, float* __restrict__ outT)
{
    int gwarp = (blockIdx.x << 3) + (threadIdx.x >> 5);
    int lane = threadIdx.x & 31;
    int b = gwarp >> 14;
    int pix = gwarp & (HWS - 1);
    int y = pix >> 7, x = pix & 127;

    float mvx = mv[(b*2 + 0)*HWS + pix];
    float mvy = mv[(b*2 + 1)*HWS + pix];
    const float inv = 2.0f / 127.0f;
    float gx = fminf(fmaxf(-1.0f + inv*(float)x + mvx*0.5f, -1.0f), 1.0f);
    float gy = fminf(fmaxf(-1.0f + inv*(float)y + mvy*0.5f, -1.0f), 1.0f);
    float px = (gx + 1.0f) * 0.5f * 127.0f;
    float py = (gy + 1.0f) * 0.5f * 127.0f;
    float fx0 = floorf(px), fy0 = floorf(py);
    float wx = px - fx0, wy = py - fy0;
    int ix0 = min(max((int)fx0, 0), WW - 1);
    int iy0 = min(max((int)fy0, 0), HH - 1);
    int ix1 = min(ix0 + 1, WW - 1);
    int iy1 = min(iy0 + 1, HH - 1);

    const float2* g2 = (const float2*)gT;
    int pbase = b * HWS;
    float2 g00 = g2[(pbase + iy0*WW + ix0)*32 + lane];
    float2 g01 = g2[(pbase + iy0*WW + ix1)*32 + lane];
    float2 g10 = g2[(pbase + iy1*WW + ix0)*32 + lane];
    float2 g11 = g2[(pbase + iy1*WW + ix1)*32 + lane];
    float w00 = (1.f-wx)*(1.f-wy), w01 = wx*(1.f-wy), w10 = (1.f-wx)*wy, w11 = wx*wy;
    float2 cv = ((const float2*)cT)[(pbase + pix)*32 + lane];
    int c0 = lane*2;
    float h1a = g00.x*w00 + g01.x*w01 + g10.x*w10 + g11.x*w11 + cv.x + b1[c0];
    float h1b = g00.y*w00 + g01.y*w01 + g10.y*w10 + g11.y*w11 + cv.y + b1[c0+1];
    h1a = h1a >= 0.f ? h1a : 0.1f*h1a;
    h1b = h1b >= 0.f ? h1b : 0.1f*h1b;

    float part[9];
#pragma unroll
    for (int j = 0; j < 9; ++j)
        part[j] = w2[j*64 + c0]*h1a + w2[j*64 + c0 + 1]*h1b;
#pragma unroll
    for (int off = 16; off > 0; off >>= 1)
#pragma unroll
        for (int j = 0; j < 9; ++j)
            part[j] += __shfl_xor_sync(0xffffffffu, part[j], off);

    float mx = -1e30f;
#pragma unroll
    for (int j = 0; j < 9; ++j) { part[j] += b2[j]; mx = fmaxf(mx, part[j]); }
    float s = 0.f;
    float attn[9];
#pragma unroll
    for (int j = 0; j < 9; ++j) { attn[j] = __expf(part[j] - mx); s += attn[j]; }
    float sc = 1.0f / (9.0f * s);
#pragma unroll
    for (int j = 0; j < 9; ++j) attn[j] *= sc;

    float wyv[2] = {1.f - wy, wy};
    float wxv[2] = {1.f - wx, wx};
    int d1y = iy1 - iy0;
    int d1x = ix1 - ix0;
    float Wrow[3][4], Wcol[3][4];
#pragma unroll
    for (int dy = 0; dy < 3; ++dy)
#pragma unroll
        for (int r = 0; r < 4; ++r) { Wrow[dy][r] = 0.f; Wcol[dy][r] = 0.f; }
#pragma unroll
    for (int dy = 0; dy < 3; ++dy) {
        int rowlo = iy0 + dy - 1;
        float vlo = (rowlo >= 0 && rowlo < HH) ? wyv[0] : 0.f;
        Wrow[dy][dy] += vlo;
        int rowhi = iy1 + dy - 1;
        float vhi = (rowhi >= 0 && rowhi < HH) ? wyv[1] : 0.f;
        if (d1y) Wrow[dy][dy+1] += vhi; else Wrow[dy][dy] += vhi;

        int collo = ix0 + dy - 1;
        float ulo = (collo >= 0 && collo < WW) ? wxv[0] : 0.f;
        Wcol[dy][dy] += ulo;
        int colhi = ix1 + dy - 1;
        float uhi = (colhi >= 0 && colhi < WW) ? wxv[1] : 0.f;
        if (d1x) Wcol[dy][dy+1] += uhi; else Wcol[dy][dy] += uhi;
    }
    float tmp[3][4];
#pragma unroll
    for (int dy = 0; dy < 3; ++dy)
#pragma unroll
        for (int sx = 0; sx < 4; ++sx) {
            float t = 0.f;
#pragma unroll
            for (int dx = 0; dx < 3; ++dx) t += attn[dy*3 + dx] * Wcol[dx][sx];
            tmp[dy][sx] = t;
        }
    float coeff[16];
#pragma unroll
    for (int r = 0; r < 4; ++r)
#pragma unroll
        for (int sx = 0; sx < 4; ++sx) {
            float t = 0.f;
#pragma unroll
            for (int dy = 0; dy < 3; ++dy) t += Wrow[dy][r] * tmp[dy][sx];
            coeff[r*4 + sx] = t;
        }

    const float2* n2 = (const float2*)nbhT;
    float oa = 0.f, ob = 0.f;
#pragma unroll
    for (int r = 0; r < 4; ++r) {
        int row = iy0 - 1 + r;
#pragma unroll
        for (int sx = 0; sx < 4; ++sx) {
            float cf = coeff[r*4 + sx];
            if (cf != 0.f) {
                int col = ix0 - 1 + sx;
                float2 v = n2[(pbase + row*WW + col)*32 + lane];
                oa += cf * v.x;
                ob += cf * v.y;
            }
        }
    }
    ((float2*)outT)[(pbase + pix)*32 + lane] = make_float2(oa, ob);
}

// ---------------- launcher ----------------
extern "C" void kernel_launch(void* const* d_in, const int* in_sizes, int n_in,
                              void* d_out, int out_size)
{
    const float* nbh = (const float*)d_in[0];
    const float* cen = (const float*)d_in[1];
    const float* mv  = (const float*)d_in[2];
    const float* w1  = (const float*)d_in[3];
    const float* b1  = (const float*)d_in[4];
    const float* w2  = (const float*)d_in[5];
    const float* b2  = (const float*)d_in[6];
    float* out = (float*)d_out;

    float *nbhT, *gT, *cT, *outT;
    __half *nh, *ch, *wc;
    cudaGetSymbolAddress((void**)&nbhT, d_nbhT);
    cudaGetSymbolAddress((void**)&gT,   d_gT);
    cudaGetSymbolAddress((void**)&cT,   d_cT);
    cudaGetSymbolAddress((void**)&outT, d_outT);
    cudaGetSymbolAddress((void**)&nh,   d_nbh_h);
    cudaGetSymbolAddress((void**)&ch,   d_cen_h);
    cudaGetSymbolAddress((void**)&wc,   d_wcomb);

    cudaFuncSetAttribute(conv_tc, cudaFuncAttributeMaxDynamicSharedMemorySize, CONV_SMEM);

    prep_w<<<2*9*4096/256, 256>>>(w1, wc);

    // NCHW -> NHWC (+ fp16 cast) for both inputs in one launch
    transpose_split2<<<dim3(HWS/32, CHC/32, 2*BB), dim3(32, 8)>>>(nbh, cen, nbhT, nh, ch);

    // HMMA dual conv: grid (2-row tile, batch, conv)
    conv_tc<<<dim3(HH/2, BB, 2), 512, CONV_SMEM>>>(nh, ch, wc, gT, cT);

    fused_attn<<<BB*HWS/8, 256>>>(gT, cT, nbhT, mv, b1, w2, b2, outT);

    // NHWC -> NCHW
    transpose_k<<<dim3(CHC/32, HWS/32, BB), dim3(32, 8)>>>(outT, out, HWS, CHC);
}

// round 6
// speedup vs baseline: 3.5294x; 1.0354x over previous
#include <cuda_runtime.h>
#include <cuda_fp16.h>
#include <cstdint>

#define BB 4
#define CHC 64
#define HH 128
#define WW 128
#define HWS (HH*WW)

// ---------------- scratch (no allocations allowed) ----------------
__device__ __align__(256) __half d_nbh_h[BB*HWS*CHC];      // NHWC fp16
__device__ __align__(256) __half d_cen_h[BB*HWS*CHC];
__device__ __align__(256) __half d_gH[BB*HWS*CHC];         // conv(nbh) NHWC fp16
__device__ __align__(256) __half d_cH[BB*HWS*CHC];         // conv(cen) NHWC fp16
__device__ __align__(256) float d_outT[BB*HWS*CHC];
__device__ __align__(256) __half d_wcomb[2*9*CHC*CHC];     // [conv][tap][o][c] fp16

// ---------------- PTX helpers (portable sm_80+ subset only) ----------------
__device__ __forceinline__ uint32_t smem_u32(const void* p) {
    uint32_t a;
    asm("{ .reg .u64 t; cvta.to.shared.u64 t, %1; cvt.u32.u64 %0, t; }" : "=r"(a) : "l"(p));
    return a;
}
__device__ __forceinline__ void cpa16(uint32_t dst, const void* src) {
    asm volatile("cp.async.cg.shared.global [%0], [%1], 16;" :: "r"(dst), "l"(src));
}
__device__ __forceinline__ void ldsm4(uint32_t* r, uint32_t addr) {
    asm volatile("ldmatrix.sync.aligned.m8n8.x4.shared.b16 {%0,%1,%2,%3}, [%4];"
        : "=r"(r[0]), "=r"(r[1]), "=r"(r[2]), "=r"(r[3]) : "r"(addr));
}
__device__ __forceinline__ void mma_fp16(float* d, const uint32_t* a, const uint32_t* b) {
    asm volatile("mma.sync.aligned.m16n8k16.row.col.f32.f16.f16.f32 "
        "{%0,%1,%2,%3}, {%4,%5,%6,%7}, {%8,%9}, {%0,%1,%2,%3};"
        : "+f"(d[0]), "+f"(d[1]), "+f"(d[2]), "+f"(d[3])
        : "r"(a[0]), "r"(a[1]), "r"(a[2]), "r"(a[3]), "r"(b[0]), "r"(b[1]));
}

// ---------------- transpose NCHW->NHWC for both inputs (fp16 cast) ----------------
// grid.z = which*4 + b. which==0: nbh; which==1: cen
__global__ void transpose_split2(const float* __restrict__ nbh, const float* __restrict__ cen,
                                 __half* __restrict__ nh, __half* __restrict__ ch)
{
    __shared__ float tile[32][33];
    int which = blockIdx.z >> 2;
    int b = blockIdx.z & 3;
    const float* in = which ? cen : nbh;
    __half* oh = which ? ch : nh;
    const float* inb = in + (size_t)b * CHC * HWS;
    int c0 = blockIdx.x * 32;   // pixel tile
    int r0 = blockIdx.y * 32;   // channel tile
#pragma unroll
    for (int i = 0; i < 32; i += 8)
        tile[threadIdx.y + i][threadIdx.x] =
            inb[(size_t)(r0 + threadIdx.y + i) * HWS + (c0 + threadIdx.x)];
    __syncthreads();
#pragma unroll
    for (int i = 0; i < 32; i += 8) {
        float v = tile[threadIdx.x][threadIdx.y + i];
        int px = c0 + threadIdx.y + i;
        int chn = r0 + threadIdx.x;
        oh[((size_t)b * HWS + px) * 64 + chn] = __float2half(v);
    }
}

// plain transpose (output NHWC -> NCHW)
__global__ void transpose_k(const float* __restrict__ in, float* __restrict__ out,
                            int R, int C)
{
    __shared__ float tile[32][33];
    int b = blockIdx.z;
    const float* inb = in + (size_t)b * R * C;
    float* outb = out + (size_t)b * R * C;
    int c0 = blockIdx.x * 32;
    int r0 = blockIdx.y * 32;
#pragma unroll
    for (int i = 0; i < 32; i += 8)
        tile[threadIdx.y + i][threadIdx.x] =
            inb[(size_t)(r0 + threadIdx.y + i) * C + (c0 + threadIdx.x)];
    __syncthreads();
#pragma unroll
    for (int i = 0; i < 32; i += 8)
        outb[(size_t)(c0 + threadIdx.y + i) * R + (r0 + threadIdx.x)] =
            tile[threadIdx.x][threadIdx.y + i];
}

// ---------------- weight prep: [conv][tap][o][c] fp16 ----------------
__global__ void prep_w(const float* __restrict__ w1, __half* __restrict__ wcomb)
{
    int idx = blockIdx.x * 256 + threadIdx.x;   // 2*9*64*64 threads
    int c = idx & 63;
    int o = (idx >> 6) & 63;
    int tap = (idx >> 12) % 9;
    int conv = idx / (9 * 4096);
    wcomb[idx] = __float2half(w1[o * 1152 + conv * 576 + c * 9 + tap]);
}

// ---------------- HMMA dual conv3x3, single-pass fp16, fp16 output ----------------
// CTA: (2-row tile, batch, conv). M=256 px, N=64. 4x4 warp grid, warp tile M64xN16.
// smem: A halo 4 rows x 130 px x 128B = 66560 B; W all 9 taps: 576 rows x 128B = 73728 B.
#define A_BYTES (520*128)
#define W_OFF   A_BYTES
#define CONV_SMEM (A_BYTES + 9*64*128)

__global__ void __launch_bounds__(512, 1) conv_tc(
    const __half* __restrict__ nbh_h,
    const __half* __restrict__ cen_h,
    const __half* __restrict__ wcomb,
    __half* __restrict__ gH, __half* __restrict__ cH)
{
    extern __shared__ char smem[];
    const int tid = threadIdx.x;
    const int lane = tid & 31;
    const int wid = tid >> 5;
    const int mwarp = wid >> 2, nwarp = wid & 3;
    const int y0 = blockIdx.x * 2;
    const int b = blockIdx.y;
    const int conv = blockIdx.z;
    const __half* src = conv ? cen_h : nbh_h;
    __half* outp = conv ? cH : gH;
    const __half* wsrc = wcomb + (size_t)conv * 9 * 4096;
    const uint32_t sb = smem_u32(smem);

    // ---- stage A: 512 px x 8 chunks of 16B, swizzled; OOB rows -> zeros ----
#pragma unroll
    for (int it = 0; it < 8; ++it) {
        int i = tid + it * 512;
        int px = i >> 3, chn = i & 7;
        int ry = px >> 7, x = px & 127;
        int yy = y0 - 1 + ry;
        int pxb = ry * 130 + x + 1;
        uint32_t off = (uint32_t)pxb * 128 + (((uint32_t)chn ^ (pxb & 7)) << 4);
        if ((unsigned)yy < 128u)
            cpa16(sb + off, src + (((size_t)((b * 128 + yy) * 128 + x)) << 6) + chn * 8);
        else
            *(uint4*)(smem + off) = make_uint4(0u, 0u, 0u, 0u);
    }
    // pad columns x=-1 and x=128 (pxb x index 0 and 129), 4 halo rows
    if (tid < 64) {
        int pp = tid >> 3;
        int ry = pp >> 1;
        int xpad = (pp & 1) ? 129 : 0;
        int pxb = ry * 130 + xpad;
        int chn = tid & 7;
        uint32_t off = (uint32_t)pxb * 128 + (((uint32_t)chn ^ (pxb & 7)) << 4);
        *(uint4*)(smem + off) = make_uint4(0u, 0u, 0u, 0u);
    }
    // ---- stage all 9 taps of W: 576 o-rows x 8 chunks ----
#pragma unroll
    for (int it = 0; it < 9; ++it) {
        int i = tid + it * 512;
        int row = i >> 3, chn = i & 7;
        uint32_t off = W_OFF + (uint32_t)row * 128 + (((uint32_t)chn ^ (row & 7)) << 4);
        cpa16(sb + off, wsrc + row * 64 + chn * 8);
    }
    asm volatile("cp.async.commit_group;");
    asm volatile("cp.async.wait_group 0;");
    __syncthreads();

    float acc[4][2][4];
#pragma unroll
    for (int mt = 0; mt < 4; ++mt)
#pragma unroll
        for (int nt = 0; nt < 2; ++nt)
#pragma unroll
            for (int q = 0; q < 4; ++q) acc[mt][nt][q] = 0.f;

    const int chalfA = lane >> 4;
    const int chalfB = (lane >> 3) & 1;
    const int o_ld = nwarp * 16 + (lane & 7) + ((lane >> 4) << 3);
    const uint32_t bsw = ((uint32_t)(o_ld & 7)) << 4;
    const uint32_t browb = sb + W_OFF + (uint32_t)o_ld * 128;

    int mbase[4], mx[4];
#pragma unroll
    for (int mt = 0; mt < 4; ++mt) {
        int m = mwarp * 64 + mt * 16 + (lane & 15);
        mbase[mt] = (m >> 7);
        mx[mt] = m & 127;
    }

#pragma unroll
    for (int t = 0; t < 9; ++t) {
        const int dy = t / 3 - 1, dx = t % 3 - 1;
        uint32_t arow[4], asw[4];
#pragma unroll
        for (int mt = 0; mt < 4; ++mt) {
            int pxb = (mbase[mt] + dy + 1) * 130 + (mx[mt] + dx + 1);
            arow[mt] = sb + (uint32_t)pxb * 128;
            asw[mt] = ((uint32_t)(pxb & 7)) << 4;
        }
        const uint32_t brow = browb + (uint32_t)t * 64 * 128;

#pragma unroll
        for (int ks = 0; ks < 4; ++ks) {
            const uint32_t chi = (uint32_t)(ks * 2 + chalfA) << 4;
            uint32_t a[4][4];
#pragma unroll
            for (int mt = 0; mt < 4; ++mt)
                ldsm4(a[mt], arow[mt] + (chi ^ asw[mt]));
            const uint32_t cbi = (uint32_t)(ks * 2 + chalfB) << 4;
            uint32_t bv[4];
            ldsm4(bv, brow + (cbi ^ bsw));
#pragma unroll
            for (int mt = 0; mt < 4; ++mt)
#pragma unroll
                for (int nt = 0; nt < 2; ++nt)
                    mma_fp16(acc[mt][nt], a[mt], &bv[nt * 2]);
        }
    }

    // ---- epilogue: fragments -> NHWC fp16 ----
#pragma unroll
    for (int mt = 0; mt < 4; ++mt) {
        int m0 = mwarp * 64 + mt * 16 + (lane >> 2);
#pragma unroll
        for (int half = 0; half < 2; ++half) {
            int m = m0 + half * 8;
            int y = y0 + (m >> 7), x = m & 127;
            __half2* rowp = (__half2*)(outp + (((size_t)((b * 128 + y) * 128 + x)) << 6));
#pragma unroll
            for (int nt = 0; nt < 2; ++nt) {
                int o = nwarp * 16 + nt * 8 + (lane & 3) * 2;
                rowp[o >> 1] = __floats2half2_rn(acc[mt][nt][half * 2], acc[mt][nt][half * 2 + 1]);
            }
        }
    }
}

// ---------------- fused: bilinear(g) + cH + b1 -> leaky -> w2 -> softmax -> gather ----------------
// one warp per pixel, lane handles channels (2*lane, 2*lane+1); all fp16 operands
__global__ void __launch_bounds__(256) fused_attn(
    const __half* __restrict__ gH, const __half* __restrict__ cH,
    const __half* __restrict__ nbh_h, const float* __restrict__ mv,
    const float* __restrict__ b1, const float* __restrict__ w2,
    const float* __restrict__ b2, float* __restrict__ outT)
{
    int gwarp = (blockIdx.x << 3) + (threadIdx.x >> 5);
    int lane = threadIdx.x & 31;
    int b = gwarp >> 14;
    int pix = gwarp & (HWS - 1);
    int y = pix >> 7, x = pix & 127;

    float mvx = mv[(b*2 + 0)*HWS + pix];
    float mvy = mv[(b*2 + 1)*HWS + pix];
    const float inv = 2.0f / 127.0f;
    float gx = fminf(fmaxf(-1.0f + inv*(float)x + mvx*0.5f, -1.0f), 1.0f);
    float gy = fminf(fmaxf(-1.0f + inv*(float)y + mvy*0.5f, -1.0f), 1.0f);
    float px = (gx + 1.0f) * 0.5f * 127.0f;
    float py = (gy + 1.0f) * 0.5f * 127.0f;
    float fx0 = floorf(px), fy0 = floorf(py);
    float wx = px - fx0, wy = py - fy0;
    int ix0 = min(max((int)fx0, 0), WW - 1);
    int iy0 = min(max((int)fy0, 0), HH - 1);
    int ix1 = min(ix0 + 1, WW - 1);
    int iy1 = min(iy0 + 1, HH - 1);

    const __half2* g2 = (const __half2*)gH;
    int pbase = b * HWS;
    float2 g00 = __half22float2(g2[(pbase + iy0*WW + ix0)*32 + lane]);
    float2 g01 = __half22float2(g2[(pbase + iy0*WW + ix1)*32 + lane]);
    float2 g10 = __half22float2(g2[(pbase + iy1*WW + ix0)*32 + lane]);
    float2 g11 = __half22float2(g2[(pbase + iy1*WW + ix1)*32 + lane]);
    float w00 = (1.f-wx)*(1.f-wy), w01 = wx*(1.f-wy), w10 = (1.f-wx)*wy, w11 = wx*wy;
    float2 cv = __half22float2(((const __half2*)cH)[(pbase + pix)*32 + lane]);
    int c0 = lane*2;
    float h1a = g00.x*w00 + g01.x*w01 + g10.x*w10 + g11.x*w11 + cv.x + b1[c0];
    float h1b = g00.y*w00 + g01.y*w01 + g10.y*w10 + g11.y*w11 + cv.y + b1[c0+1];
    h1a = h1a >= 0.f ? h1a : 0.1f*h1a;
    h1b = h1b >= 0.f ? h1b : 0.1f*h1b;

    float part[9];
#pragma unroll
    for (int j = 0; j < 9; ++j)
        part[j] = w2[j*64 + c0]*h1a + w2[j*64 + c0 + 1]*h1b;
#pragma unroll
    for (int off = 16; off > 0; off >>= 1)
#pragma unroll
        for (int j = 0; j < 9; ++j)
            part[j] += __shfl_xor_sync(0xffffffffu, part[j], off);

    float mx = -1e30f;
#pragma unroll
    for (int j = 0; j < 9; ++j) { part[j] += b2[j]; mx = fmaxf(mx, part[j]); }
    float s = 0.f;
    float attn[9];
#pragma unroll
    for (int j = 0; j < 9; ++j) { attn[j] = __expf(part[j] - mx); s += attn[j]; }
    float sc = 1.0f / (9.0f * s);
#pragma unroll
    for (int j = 0; j < 9; ++j) attn[j] *= sc;

    float wyv[2] = {1.f - wy, wy};
    float wxv[2] = {1.f - wx, wx};
    int d1y = iy1 - iy0;
    int d1x = ix1 - ix0;
    float Wrow[3][4], Wcol[3][4];
#pragma unroll
    for (int dy = 0; dy < 3; ++dy)
#pragma unroll
        for (int r = 0; r < 4; ++r) { Wrow[dy][r] = 0.f; Wcol[dy][r] = 0.f; }
#pragma unroll
    for (int dy = 0; dy < 3; ++dy) {
        int rowlo = iy0 + dy - 1;
        float vlo = (rowlo >= 0 && rowlo < HH) ? wyv[0] : 0.f;
        Wrow[dy][dy] += vlo;
        int rowhi = iy1 + dy - 1;
        float vhi = (rowhi >= 0 && rowhi < HH) ? wyv[1] : 0.f;
        if (d1y) Wrow[dy][dy+1] += vhi; else Wrow[dy][dy] += vhi;

        int collo = ix0 + dy - 1;
        float ulo = (collo >= 0 && collo < WW) ? wxv[0] : 0.f;
        Wcol[dy][dy] += ulo;
        int colhi = ix1 + dy - 1;
        float uhi = (colhi >= 0 && colhi < WW) ? wxv[1] : 0.f;
        if (d1x) Wcol[dy][dy+1] += uhi; else Wcol[dy][dy] += uhi;
    }
    float tmp[3][4];
#pragma unroll
    for (int dy = 0; dy < 3; ++dy)
#pragma unroll
        for (int sx = 0; sx < 4; ++sx) {
            float t = 0.f;
#pragma unroll
            for (int dx = 0; dx < 3; ++dx) t += attn[dy*3 + dx] * Wcol[dx][sx];
            tmp[dy][sx] = t;
        }
    float coeff[16];
#pragma unroll
    for (int r = 0; r < 4; ++r)
#pragma unroll
        for (int sx = 0; sx < 4; ++sx) {
            float t = 0.f;
#pragma unroll
            for (int dy = 0; dy < 3; ++dy) t += Wrow[dy][r] * tmp[dy][sx];
            coeff[r*4 + sx] = t;
        }

    const __half2* n2 = (const __half2*)nbh_h;
    float oa = 0.f, ob = 0.f;
#pragma unroll
    for (int r = 0; r < 4; ++r) {
        int row = iy0 - 1 + r;
#pragma unroll
        for (int sx = 0; sx < 4; ++sx) {
            float cf = coeff[r*4 + sx];
            if (cf != 0.f) {
                int col = ix0 - 1 + sx;
                float2 v = __half22float2(n2[(pbase + row*WW + col)*32 + lane]);
                oa += cf * v.x;
                ob += cf * v.y;
            }
        }
    }
    ((float2*)outT)[(pbase + pix)*32 + lane] = make_float2(oa, ob);
}

// ---------------- launcher ----------------
extern "C" void kernel_launch(void* const* d_in, const int* in_sizes, int n_in,
                              void* d_out, int out_size)
{
    const float* nbh = (const float*)d_in[0];
    const float* cen = (const float*)d_in[1];
    const float* mv  = (const float*)d_in[2];
    const float* w1  = (const float*)d_in[3];
    const float* b1  = (const float*)d_in[4];
    const float* w2  = (const float*)d_in[5];
    const float* b2  = (const float*)d_in[6];
    float* out = (float*)d_out;

    float *outT;
    __half *nh, *ch, *gH, *cH, *wc;
    cudaGetSymbolAddress((void**)&outT, d_outT);
    cudaGetSymbolAddress((void**)&nh,   d_nbh_h);
    cudaGetSymbolAddress((void**)&ch,   d_cen_h);
    cudaGetSymbolAddress((void**)&gH,   d_gH);
    cudaGetSymbolAddress((void**)&cH,   d_cH);
    cudaGetSymbolAddress((void**)&wc,   d_wcomb);

    cudaFuncSetAttribute(conv_tc, cudaFuncAttributeMaxDynamicSharedMemorySize, CONV_SMEM);

    prep_w<<<2*9*4096/256, 256>>>(w1, wc);

    // NCHW -> NHWC fp16 for both inputs in one launch
    transpose_split2<<<dim3(HWS/32, CHC/32, 2*BB), dim3(32, 8)>>>(nbh, cen, nh, ch);

    // HMMA dual conv: grid (2-row tile, batch, conv)
    conv_tc<<<dim3(HH/2, BB, 2), 512, CONV_SMEM>>>(nh, ch, wc, gH, cH);

    fused_attn<<<BB*HWS/8, 256>>>(gH, cH, nh, mv, b1, w2, b2, outT);

    // NHWC -> NCHW
    transpose_k<<<dim3(CHC/32, HWS/32, BB), dim3(32, 8)>>>(outT, out, HWS, CHC);
}

// round 7
// speedup vs baseline: 4.3222x; 1.2246x over previous
#include <cuda_runtime.h>
#include <cuda_fp16.h>
#include <cstdint>

#define BB 4
#define CHC 64
#define HH 128
#define WW 128
#define HWS (HH*WW)

// ---------------- scratch (no allocations allowed) ----------------
__device__ __align__(256) __half d_nbh_h[BB*HWS*CHC];      // NHWC fp16
__device__ __align__(256) __half d_cen_h[BB*HWS*CHC];
__device__ __align__(256) __half d_gH[BB*HWS*CHC];         // conv(nbh) NHWC fp16
__device__ __align__(256) __half d_cH[BB*HWS*CHC];         // conv(cen) NHWC fp16
__device__ __align__(256) float d_outT[BB*HWS*CHC];
__device__ __align__(256) __half d_wcomb[2*9*CHC*CHC];     // [conv][tap][o][c] fp16
__device__ __align__(256) __half d_w2h[9*CHC];             // w2 fp16

// ---------------- PTX helpers (portable sm_80+ subset only) ----------------
__device__ __forceinline__ uint32_t smem_u32(const void* p) {
    uint32_t a;
    asm("{ .reg .u64 t; cvta.to.shared.u64 t, %1; cvt.u32.u64 %0, t; }" : "=r"(a) : "l"(p));
    return a;
}
__device__ __forceinline__ void cpa16(uint32_t dst, const void* src) {
    asm volatile("cp.async.cg.shared.global [%0], [%1], 16;" :: "r"(dst), "l"(src));
}
__device__ __forceinline__ void ldsm4(uint32_t* r, uint32_t addr) {
    asm volatile("ldmatrix.sync.aligned.m8n8.x4.shared.b16 {%0,%1,%2,%3}, [%4];"
        : "=r"(r[0]), "=r"(r[1]), "=r"(r[2]), "=r"(r[3]) : "r"(addr));
}
__device__ __forceinline__ void mma_fp16(float* d, const uint32_t* a, const uint32_t* b) {
    asm volatile("mma.sync.aligned.m16n8k16.row.col.f32.f16.f16.f32 "
        "{%0,%1,%2,%3}, {%4,%5,%6,%7}, {%8,%9}, {%0,%1,%2,%3};"
        : "+f"(d[0]), "+f"(d[1]), "+f"(d[2]), "+f"(d[3])
        : "r"(a[0]), "r"(a[1]), "r"(a[2]), "r"(a[3]), "r"(b[0]), "r"(b[1]));
}
__device__ __forceinline__ void h8_to_f(const uint4& u, float* f) {
    const __half2* h = (const __half2*)&u;
    float2 t;
    t = __half22float2(h[0]); f[0] = t.x; f[1] = t.y;
    t = __half22float2(h[1]); f[2] = t.x; f[3] = t.y;
    t = __half22float2(h[2]); f[4] = t.x; f[5] = t.y;
    t = __half22float2(h[3]); f[6] = t.x; f[7] = t.y;
}

// ---------------- transpose NCHW->NHWC for both inputs (fp16 cast) ----------------
__global__ void transpose_split2(const float* __restrict__ nbh, const float* __restrict__ cen,
                                 __half* __restrict__ nh, __half* __restrict__ ch)
{
    __shared__ float tile[32][33];
    int which = blockIdx.z >> 2;
    int b = blockIdx.z & 3;
    const float* in = which ? cen : nbh;
    __half* oh = which ? ch : nh;
    const float* inb = in + (size_t)b * CHC * HWS;
    int c0 = blockIdx.x * 32;
    int r0 = blockIdx.y * 32;
#pragma unroll
    for (int i = 0; i < 32; i += 8)
        tile[threadIdx.y + i][threadIdx.x] =
            inb[(size_t)(r0 + threadIdx.y + i) * HWS + (c0 + threadIdx.x)];
    __syncthreads();
#pragma unroll
    for (int i = 0; i < 32; i += 8) {
        float v = tile[threadIdx.x][threadIdx.y + i];
        int px = c0 + threadIdx.y + i;
        int chn = r0 + threadIdx.x;
        oh[((size_t)b * HWS + px) * 64 + chn] = __float2half(v);
    }
}

// plain transpose (output NHWC -> NCHW)
__global__ void transpose_k(const float* __restrict__ in, float* __restrict__ out,
                            int R, int C)
{
    __shared__ float tile[32][33];
    int b = blockIdx.z;
    const float* inb = in + (size_t)b * R * C;
    float* outb = out + (size_t)b * R * C;
    int c0 = blockIdx.x * 32;
    int r0 = blockIdx.y * 32;
#pragma unroll
    for (int i = 0; i < 32; i += 8)
        tile[threadIdx.y + i][threadIdx.x] =
            inb[(size_t)(r0 + threadIdx.y + i) * C + (c0 + threadIdx.x)];
    __syncthreads();
#pragma unroll
    for (int i = 0; i < 32; i += 8)
        outb[(size_t)(c0 + threadIdx.y + i) * R + (r0 + threadIdx.x)] =
            tile[threadIdx.x][threadIdx.y + i];
}

// ---------------- weight prep: conv weights + w2 -> fp16 ----------------
__global__ void prep_w(const float* __restrict__ w1, const float* __restrict__ w2,
                       __half* __restrict__ wcomb, __half* __restrict__ w2h)
{
    int idx = blockIdx.x * 256 + threadIdx.x;
    if (idx < 2*9*4096) {
        int c = idx & 63;
        int o = (idx >> 6) & 63;
        int tap = (idx >> 12) % 9;
        int conv = idx / (9 * 4096);
        wcomb[idx] = __float2half(w1[o * 1152 + conv * 576 + c * 9 + tap]);
    } else {
        int k = idx - 2*9*4096;
        if (k < 9*CHC) w2h[k] = __float2half(w2[k]);
    }
}

// ---------------- HMMA dual conv3x3, single-pass fp16, fp16 output ----------------
#define A_BYTES (520*128)
#define W_OFF   A_BYTES
#define CONV_SMEM (A_BYTES + 9*64*128)

__global__ void __launch_bounds__(512, 1) conv_tc(
    const __half* __restrict__ nbh_h,
    const __half* __restrict__ cen_h,
    const __half* __restrict__ wcomb,
    __half* __restrict__ gH, __half* __restrict__ cH)
{
    extern __shared__ char smem[];
    const int tid = threadIdx.x;
    const int lane = tid & 31;
    const int wid = tid >> 5;
    const int mwarp = wid >> 2, nwarp = wid & 3;
    const int y0 = blockIdx.x * 2;
    const int b = blockIdx.y;
    const int conv = blockIdx.z;
    const __half* src = conv ? cen_h : nbh_h;
    __half* outp = conv ? cH : gH;
    const __half* wsrc = wcomb + (size_t)conv * 9 * 4096;
    const uint32_t sb = smem_u32(smem);

#pragma unroll
    for (int it = 0; it < 8; ++it) {
        int i = tid + it * 512;
        int px = i >> 3, chn = i & 7;
        int ry = px >> 7, x = px & 127;
        int yy = y0 - 1 + ry;
        int pxb = ry * 130 + x + 1;
        uint32_t off = (uint32_t)pxb * 128 + (((uint32_t)chn ^ (pxb & 7)) << 4);
        if ((unsigned)yy < 128u)
            cpa16(sb + off, src + (((size_t)((b * 128 + yy) * 128 + x)) << 6) + chn * 8);
        else
            *(uint4*)(smem + off) = make_uint4(0u, 0u, 0u, 0u);
    }
    if (tid < 64) {
        int pp = tid >> 3;
        int ry = pp >> 1;
        int xpad = (pp & 1) ? 129 : 0;
        int pxb = ry * 130 + xpad;
        int chn = tid & 7;
        uint32_t off = (uint32_t)pxb * 128 + (((uint32_t)chn ^ (pxb & 7)) << 4);
        *(uint4*)(smem + off) = make_uint4(0u, 0u, 0u, 0u);
    }
#pragma unroll
    for (int it = 0; it < 9; ++it) {
        int i = tid + it * 512;
        int row = i >> 3, chn = i & 7;
        uint32_t off = W_OFF + (uint32_t)row * 128 + (((uint32_t)chn ^ (row & 7)) << 4);
        cpa16(sb + off, wsrc + row * 64 + chn * 8);
    }
    asm volatile("cp.async.commit_group;");
    asm volatile("cp.async.wait_group 0;");
    __syncthreads();

    float acc[4][2][4];
#pragma unroll
    for (int mt = 0; mt < 4; ++mt)
#pragma unroll
        for (int nt = 0; nt < 2; ++nt)
#pragma unroll
            for (int q = 0; q < 4; ++q) acc[mt][nt][q] = 0.f;

    const int chalfA = lane >> 4;
    const int chalfB = (lane >> 3) & 1;
    const int o_ld = nwarp * 16 + (lane & 7) + ((lane >> 4) << 3);
    const uint32_t bsw = ((uint32_t)(o_ld & 7)) << 4;
    const uint32_t browb = sb + W_OFF + (uint32_t)o_ld * 128;

    int mbase[4], mx[4];
#pragma unroll
    for (int mt = 0; mt < 4; ++mt) {
        int m = mwarp * 64 + mt * 16 + (lane & 15);
        mbase[mt] = (m >> 7);
        mx[mt] = m & 127;
    }

#pragma unroll
    for (int t = 0; t < 9; ++t) {
        const int dy = t / 3 - 1, dx = t % 3 - 1;
        uint32_t arow[4], asw[4];
#pragma unroll
        for (int mt = 0; mt < 4; ++mt) {
            int pxb = (mbase[mt] + dy + 1) * 130 + (mx[mt] + dx + 1);
            arow[mt] = sb + (uint32_t)pxb * 128;
            asw[mt] = ((uint32_t)(pxb & 7)) << 4;
        }
        const uint32_t brow = browb + (uint32_t)t * 64 * 128;

#pragma unroll
        for (int ks = 0; ks < 4; ++ks) {
            const uint32_t chi = (uint32_t)(ks * 2 + chalfA) << 4;
            uint32_t a[4][4];
#pragma unroll
            for (int mt = 0; mt < 4; ++mt)
                ldsm4(a[mt], arow[mt] + (chi ^ asw[mt]));
            const uint32_t cbi = (uint32_t)(ks * 2 + chalfB) << 4;
            uint32_t bv[4];
            ldsm4(bv, brow + (cbi ^ bsw));
#pragma unroll
            for (int mt = 0; mt < 4; ++mt)
#pragma unroll
                for (int nt = 0; nt < 2; ++nt)
                    mma_fp16(acc[mt][nt], a[mt], &bv[nt * 2]);
        }
    }

#pragma unroll
    for (int mt = 0; mt < 4; ++mt) {
        int m0 = mwarp * 64 + mt * 16 + (lane >> 2);
#pragma unroll
        for (int half = 0; half < 2; ++half) {
            int m = m0 + half * 8;
            int y = y0 + (m >> 7), x = m & 127;
            __half2* rowp = (__half2*)(outp + (((size_t)((b * 128 + y) * 128 + x)) << 6));
#pragma unroll
            for (int nt = 0; nt < 2; ++nt) {
                int o = nwarp * 16 + nt * 8 + (lane & 3) * 2;
                rowp[o >> 1] = __floats2half2_rn(acc[mt][nt][half * 2], acc[mt][nt][half * 2 + 1]);
            }
        }
    }
}

// ---------------- fused attn: 4 pixels/warp, 8 lanes/pixel, 8 channels/lane ----------------
__global__ void __launch_bounds__(256) fused_attn(
    const __half* __restrict__ gH, const __half* __restrict__ cH,
    const __half* __restrict__ nbh_h, const float* __restrict__ mv,
    const float* __restrict__ b1, const __half* __restrict__ w2h,
    const float* __restrict__ b2, float* __restrict__ outT)
{
    int wg = blockIdx.x * 8 + (threadIdx.x >> 5);
    int lane = threadIdx.x & 31;
    int grp = lane >> 3;          // pixel within warp
    int lg = lane & 7;            // lane within pixel group; channels lg*8..lg*8+7
    int pixg = wg * 4 + grp;
    int b = pixg >> 14;
    int pix = pixg & (HWS - 1);
    int y = pix >> 7, x = pix & 127;

    float mvx = mv[(b*2 + 0)*HWS + pix];
    float mvy = mv[(b*2 + 1)*HWS + pix];
    const float inv = 2.0f / 127.0f;
    float gx = fminf(fmaxf(-1.0f + inv*(float)x + mvx*0.5f, -1.0f), 1.0f);
    float gy = fminf(fmaxf(-1.0f + inv*(float)y + mvy*0.5f, -1.0f), 1.0f);
    float px = (gx + 1.0f) * 0.5f * 127.0f;
    float py = (gy + 1.0f) * 0.5f * 127.0f;
    float fx0 = floorf(px), fy0 = floorf(py);
    float wx = px - fx0, wy = py - fy0;
    int ix0 = min(max((int)fx0, 0), WW - 1);
    int iy0 = min(max((int)fy0, 0), HH - 1);
    int ix1 = min(ix0 + 1, WW - 1);
    int iy1 = min(iy0 + 1, HH - 1);

    int pbase = b * HWS;
    const uint4* g4 = (const uint4*)gH;
    uint4 r00 = g4[(size_t)(pbase + iy0*WW + ix0)*8 + lg];
    uint4 r01 = g4[(size_t)(pbase + iy0*WW + ix1)*8 + lg];
    uint4 r10 = g4[(size_t)(pbase + iy1*WW + ix0)*8 + lg];
    uint4 r11 = g4[(size_t)(pbase + iy1*WW + ix1)*8 + lg];
    uint4 rcn = ((const uint4*)cH)[(size_t)(pbase + pix)*8 + lg];
    float w00 = (1.f-wx)*(1.f-wy), w01 = wx*(1.f-wy), w10 = (1.f-wx)*wy, w11 = wx*wy;

    float f00[8], f01[8], f10[8], f11[8], fcn[8];
    h8_to_f(r00, f00); h8_to_f(r01, f01); h8_to_f(r10, f10); h8_to_f(r11, f11);
    h8_to_f(rcn, fcn);
    float4 b1a = ((const float4*)b1)[lg*2];
    float4 b1b = ((const float4*)b1)[lg*2 + 1];
    float b1v[8] = {b1a.x, b1a.y, b1a.z, b1a.w, b1b.x, b1b.y, b1b.z, b1b.w};

    float h1[8];
#pragma unroll
    for (int i = 0; i < 8; ++i) {
        float v = f00[i]*w00 + f01[i]*w01 + f10[i]*w10 + f11[i]*w11 + fcn[i] + b1v[i];
        h1[i] = v >= 0.f ? v : 0.1f*v;
    }

    float part[9];
    const uint4* w24 = (const uint4*)w2h;
#pragma unroll
    for (int j = 0; j < 9; ++j) {
        float wv[8];
        h8_to_f(w24[j*8 + lg], wv);
        float s = h1[0]*wv[0] + h1[1]*wv[1] + h1[2]*wv[2] + h1[3]*wv[3]
                + h1[4]*wv[4] + h1[5]*wv[5] + h1[6]*wv[6] + h1[7]*wv[7];
        part[j] = s;
    }
#pragma unroll
    for (int off = 1; off < 8; off <<= 1)
#pragma unroll
        for (int j = 0; j < 9; ++j)
            part[j] += __shfl_xor_sync(0xffffffffu, part[j], off);

    float mx = -1e30f;
#pragma unroll
    for (int j = 0; j < 9; ++j) { part[j] += b2[j]; mx = fmaxf(mx, part[j]); }
    float s = 0.f;
    float attn[9];
#pragma unroll
    for (int j = 0; j < 9; ++j) { attn[j] = __expf(part[j] - mx); s += attn[j]; }
    float sc = 1.0f / (9.0f * s);
#pragma unroll
    for (int j = 0; j < 9; ++j) attn[j] *= sc;

    float wyv[2] = {1.f - wy, wy};
    float wxv[2] = {1.f - wx, wx};
    int d1y = iy1 - iy0;
    int d1x = ix1 - ix0;
    float Wrow[3][4], Wcol[3][4];
#pragma unroll
    for (int dy = 0; dy < 3; ++dy)
#pragma unroll
        for (int r = 0; r < 4; ++r) { Wrow[dy][r] = 0.f; Wcol[dy][r] = 0.f; }
#pragma unroll
    for (int dy = 0; dy < 3; ++dy) {
        int rowlo = iy0 + dy - 1;
        float vlo = (rowlo >= 0 && rowlo < HH) ? wyv[0] : 0.f;
        Wrow[dy][dy] += vlo;
        int rowhi = iy1 + dy - 1;
        float vhi = (rowhi >= 0 && rowhi < HH) ? wyv[1] : 0.f;
        if (d1y) Wrow[dy][dy+1] += vhi; else Wrow[dy][dy] += vhi;

        int collo = ix0 + dy - 1;
        float ulo = (collo >= 0 && collo < WW) ? wxv[0] : 0.f;
        Wcol[dy][dy] += ulo;
        int colhi = ix1 + dy - 1;
        float uhi = (colhi >= 0 && colhi < WW) ? wxv[1] : 0.f;
        if (d1x) Wcol[dy][dy+1] += uhi; else Wcol[dy][dy] += uhi;
    }
    float tmp[3][4];
#pragma unroll
    for (int dy = 0; dy < 3; ++dy)
#pragma unroll
        for (int sx = 0; sx < 4; ++sx) {
            float t = 0.f;
#pragma unroll
            for (int dx = 0; dx < 3; ++dx) t += attn[dy*3 + dx] * Wcol[dx][sx];
            tmp[dy][sx] = t;
        }
    float coeff[16];
#pragma unroll
    for (int r = 0; r < 4; ++r)
#pragma unroll
        for (int sx = 0; sx < 4; ++sx) {
            float t = 0.f;
#pragma unroll
            for (int dy = 0; dy < 3; ++dy) t += Wrow[dy][r] * tmp[dy][sx];
            coeff[r*4 + sx] = t;
        }

    // gather: clamped indices; OOB slots have coeff exactly 0
    int rowi[4], coli[4];
#pragma unroll
    for (int r = 0; r < 4; ++r) rowi[r] = min(max(iy0 - 1 + r, 0), HH - 1);
#pragma unroll
    for (int sx = 0; sx < 4; ++sx) coli[sx] = min(max(ix0 - 1 + sx, 0), WW - 1);

    const uint4* n4 = (const uint4*)nbh_h;
    float o[8];
#pragma unroll
    for (int i = 0; i < 8; ++i) o[i] = 0.f;
#pragma unroll
    for (int r = 0; r < 4; ++r) {
        size_t rb = (size_t)(pbase + rowi[r]*WW)*8 + lg;
#pragma unroll
        for (int sx = 0; sx < 4; ++sx) {
            uint4 v = n4[rb + (size_t)coli[sx]*8];
            float fv[8];
            h8_to_f(v, fv);
            float cf = coeff[r*4 + sx];
#pragma unroll
            for (int i = 0; i < 8; ++i) o[i] += cf * fv[i];
        }
    }
    float4* op = (float4*)(outT + (size_t)(pbase + pix)*64 + lg*8);
    op[0] = make_float4(o[0], o[1], o[2], o[3]);
    op[1] = make_float4(o[4], o[5], o[6], o[7]);
}

// ---------------- launcher ----------------
extern "C" void kernel_launch(void* const* d_in, const int* in_sizes, int n_in,
                              void* d_out, int out_size)
{
    const float* nbh = (const float*)d_in[0];
    const float* cen = (const float*)d_in[1];
    const float* mv  = (const float*)d_in[2];
    const float* w1  = (const float*)d_in[3];
    const float* b1  = (const float*)d_in[4];
    const float* w2  = (const float*)d_in[5];
    const float* b2  = (const float*)d_in[6];
    float* out = (float*)d_out;

    float *outT;
    __half *nh, *ch, *gH, *cH, *wc, *w2h;
    cudaGetSymbolAddress((void**)&outT, d_outT);
    cudaGetSymbolAddress((void**)&nh,   d_nbh_h);
    cudaGetSymbolAddress((void**)&ch,   d_cen_h);
    cudaGetSymbolAddress((void**)&gH,   d_gH);
    cudaGetSymbolAddress((void**)&cH,   d_cH);
    cudaGetSymbolAddress((void**)&wc,   d_wcomb);
    cudaGetSymbolAddress((void**)&w2h,  d_w2h);

    cudaFuncSetAttribute(conv_tc, cudaFuncAttributeMaxDynamicSharedMemorySize, CONV_SMEM);

    prep_w<<<(2*9*4096 + 9*CHC + 255)/256, 256>>>(w1, w2, wc, w2h);

    // NCHW -> NHWC fp16 for both inputs in one launch
    transpose_split2<<<dim3(HWS/32, CHC/32, 2*BB), dim3(32, 8)>>>(nbh, cen, nh, ch);

    // HMMA dual conv: grid (2-row tile, batch, conv)
    conv_tc<<<dim3(HH/2, BB, 2), 512, CONV_SMEM>>>(nh, ch, wc, gH, cH);

    // 4 px/warp, 8 warps/block -> 32 px/block
    fused_attn<<<BB*HWS/32, 256>>>(gH, cH, nh, mv, b1, w2h, b2, outT);

    // NHWC -> NCHW
    transpose_k<<<dim3(CHC/32, HWS/32, BB), dim3(32, 8)>>>(outT, out, HWS, CHC);
}

// round 8
// speedup vs baseline: 4.7980x; 1.1101x over previous
#include <cuda_runtime.h>
#include <cuda_fp16.h>
#include <cstdint>

#define BB 4
#define CHC 64
#define HH 128
#define WW 128
#define HWS (HH*WW)

// ---------------- scratch (no allocations allowed) ----------------
__device__ __align__(256) __half d_nbh_h[BB*HWS*CHC];      // NHWC fp16
__device__ __align__(256) __half d_cen_h[BB*HWS*CHC];
__device__ __align__(256) __half d_gH[BB*HWS*CHC];         // conv(nbh) NHWC fp16
__device__ __align__(256) __half d_cH[BB*HWS*CHC];         // conv(cen) NHWC fp16
__device__ __align__(256) __half d_wcomb[2*9*CHC*CHC];     // [conv][tap][o][c] fp16
__device__ __align__(256) __half d_w2h[9*CHC];             // w2 fp16

// ---------------- PTX helpers (portable sm_80+ subset only) ----------------
__device__ __forceinline__ uint32_t smem_u32(const void* p) {
    uint32_t a;
    asm("{ .reg .u64 t; cvta.to.shared.u64 t, %1; cvt.u32.u64 %0, t; }" : "=r"(a) : "l"(p));
    return a;
}
__device__ __forceinline__ void cpa16(uint32_t dst, const void* src) {
    asm volatile("cp.async.cg.shared.global [%0], [%1], 16;" :: "r"(dst), "l"(src));
}
__device__ __forceinline__ void ldsm4(uint32_t* r, uint32_t addr) {
    asm volatile("ldmatrix.sync.aligned.m8n8.x4.shared.b16 {%0,%1,%2,%3}, [%4];"
        : "=r"(r[0]), "=r"(r[1]), "=r"(r[2]), "=r"(r[3]) : "r"(addr));
}
__device__ __forceinline__ void mma_fp16(float* d, const uint32_t* a, const uint32_t* b) {
    asm volatile("mma.sync.aligned.m16n8k16.row.col.f32.f16.f16.f32 "
        "{%0,%1,%2,%3}, {%4,%5,%6,%7}, {%8,%9}, {%0,%1,%2,%3};"
        : "+f"(d[0]), "+f"(d[1]), "+f"(d[2]), "+f"(d[3])
        : "r"(a[0]), "r"(a[1]), "r"(a[2]), "r"(a[3]), "r"(b[0]), "r"(b[1]));
}
__device__ __forceinline__ void h8_to_f(const uint4& u, float* f) {
    const __half2* h = (const __half2*)&u;
    float2 t;
    t = __half22float2(h[0]); f[0] = t.x; f[1] = t.y;
    t = __half22float2(h[1]); f[2] = t.x; f[3] = t.y;
    t = __half22float2(h[2]); f[4] = t.x; f[5] = t.y;
    t = __half22float2(h[3]); f[6] = t.x; f[7] = t.y;
}

// ---------------- transpose NCHW->NHWC for both inputs (fp16 cast) ----------------
__global__ void transpose_split2(const float* __restrict__ nbh, const float* __restrict__ cen,
                                 __half* __restrict__ nh, __half* __restrict__ ch)
{
    __shared__ float tile[32][33];
    int which = blockIdx.z >> 2;
    int b = blockIdx.z & 3;
    const float* in = which ? cen : nbh;
    __half* oh = which ? ch : nh;
    const float* inb = in + (size_t)b * CHC * HWS;
    int c0 = blockIdx.x * 32;
    int r0 = blockIdx.y * 32;
#pragma unroll
    for (int i = 0; i < 32; i += 8)
        tile[threadIdx.y + i][threadIdx.x] =
            inb[(size_t)(r0 + threadIdx.y + i) * HWS + (c0 + threadIdx.x)];
    __syncthreads();
#pragma unroll
    for (int i = 0; i < 32; i += 8) {
        float v = tile[threadIdx.x][threadIdx.y + i];
        int px = c0 + threadIdx.y + i;
        int chn = r0 + threadIdx.x;
        oh[((size_t)b * HWS + px) * 64 + chn] = __float2half(v);
    }
}

// ---------------- weight prep: conv weights + w2 -> fp16 ----------------
__global__ void prep_w(const float* __restrict__ w1, const float* __restrict__ w2,
                       __half* __restrict__ wcomb, __half* __restrict__ w2h)
{
    int idx = blockIdx.x * 256 + threadIdx.x;
    if (idx < 2*9*4096) {
        int c = idx & 63;
        int o = (idx >> 6) & 63;
        int tap = (idx >> 12) % 9;
        int conv = idx / (9 * 4096);
        wcomb[idx] = __float2half(w1[o * 1152 + conv * 576 + c * 9 + tap]);
    } else {
        int k = idx - 2*9*4096;
        if (k < 9*CHC) w2h[k] = __float2half(w2[k]);
    }
}

// ---------------- HMMA dual conv3x3, single-pass fp16, fp16 output ----------------
#define A_BYTES (520*128)
#define W_OFF   A_BYTES
#define CONV_SMEM (A_BYTES + 9*64*128)

__global__ void __launch_bounds__(512, 1) conv_tc(
    const __half* __restrict__ nbh_h,
    const __half* __restrict__ cen_h,
    const __half* __restrict__ wcomb,
    __half* __restrict__ gH, __half* __restrict__ cH)
{
    extern __shared__ char smem[];
    const int tid = threadIdx.x;
    const int lane = tid & 31;
    const int wid = tid >> 5;
    const int mwarp = wid >> 2, nwarp = wid & 3;
    const int y0 = blockIdx.x * 2;
    const int b = blockIdx.y;
    const int conv = blockIdx.z;
    const __half* src = conv ? cen_h : nbh_h;
    __half* outp = conv ? cH : gH;
    const __half* wsrc = wcomb + (size_t)conv * 9 * 4096;
    const uint32_t sb = smem_u32(smem);

#pragma unroll
    for (int it = 0; it < 8; ++it) {
        int i = tid + it * 512;
        int px = i >> 3, chn = i & 7;
        int ry = px >> 7, x = px & 127;
        int yy = y0 - 1 + ry;
        int pxb = ry * 130 + x + 1;
        uint32_t off = (uint32_t)pxb * 128 + (((uint32_t)chn ^ (pxb & 7)) << 4);
        if ((unsigned)yy < 128u)
            cpa16(sb + off, src + (((size_t)((b * 128 + yy) * 128 + x)) << 6) + chn * 8);
        else
            *(uint4*)(smem + off) = make_uint4(0u, 0u, 0u, 0u);
    }
    if (tid < 64) {
        int pp = tid >> 3;
        int ry = pp >> 1;
        int xpad = (pp & 1) ? 129 : 0;
        int pxb = ry * 130 + xpad;
        int chn = tid & 7;
        uint32_t off = (uint32_t)pxb * 128 + (((uint32_t)chn ^ (pxb & 7)) << 4);
        *(uint4*)(smem + off) = make_uint4(0u, 0u, 0u, 0u);
    }
#pragma unroll
    for (int it = 0; it < 9; ++it) {
        int i = tid + it * 512;
        int row = i >> 3, chn = i & 7;
        uint32_t off = W_OFF + (uint32_t)row * 128 + (((uint32_t)chn ^ (row & 7)) << 4);
        cpa16(sb + off, wsrc + row * 64 + chn * 8);
    }
    asm volatile("cp.async.commit_group;");
    asm volatile("cp.async.wait_group 0;");
    __syncthreads();

    float acc[4][2][4];
#pragma unroll
    for (int mt = 0; mt < 4; ++mt)
#pragma unroll
        for (int nt = 0; nt < 2; ++nt)
#pragma unroll
            for (int q = 0; q < 4; ++q) acc[mt][nt][q] = 0.f;

    const int chalfA = lane >> 4;
    const int chalfB = (lane >> 3) & 1;
    const int o_ld = nwarp * 16 + (lane & 7) + ((lane >> 4) << 3);
    const uint32_t bsw = ((uint32_t)(o_ld & 7)) << 4;
    const uint32_t browb = sb + W_OFF + (uint32_t)o_ld * 128;

    int mbase[4], mx[4];
#pragma unroll
    for (int mt = 0; mt < 4; ++mt) {
        int m = mwarp * 64 + mt * 16 + (lane & 15);
        mbase[mt] = (m >> 7);
        mx[mt] = m & 127;
    }

#pragma unroll
    for (int t = 0; t < 9; ++t) {
        const int dy = t / 3 - 1, dx = t % 3 - 1;
        uint32_t arow[4], asw[4];
#pragma unroll
        for (int mt = 0; mt < 4; ++mt) {
            int pxb = (mbase[mt] + dy + 1) * 130 + (mx[mt] + dx + 1);
            arow[mt] = sb + (uint32_t)pxb * 128;
            asw[mt] = ((uint32_t)(pxb & 7)) << 4;
        }
        const uint32_t brow = browb + (uint32_t)t * 64 * 128;

#pragma unroll
        for (int ks = 0; ks < 4; ++ks) {
            const uint32_t chi = (uint32_t)(ks * 2 + chalfA) << 4;
            uint32_t a[4][4];
#pragma unroll
            for (int mt = 0; mt < 4; ++mt)
                ldsm4(a[mt], arow[mt] + (chi ^ asw[mt]));
            const uint32_t cbi = (uint32_t)(ks * 2 + chalfB) << 4;
            uint32_t bv[4];
            ldsm4(bv, brow + (cbi ^ bsw));
#pragma unroll
            for (int mt = 0; mt < 4; ++mt)
#pragma unroll
                for (int nt = 0; nt < 2; ++nt)
                    mma_fp16(acc[mt][nt], a[mt], &bv[nt * 2]);
        }
    }

#pragma unroll
    for (int mt = 0; mt < 4; ++mt) {
        int m0 = mwarp * 64 + mt * 16 + (lane >> 2);
#pragma unroll
        for (int half = 0; half < 2; ++half) {
            int m = m0 + half * 8;
            int y = y0 + (m >> 7), x = m & 127;
            __half2* rowp = (__half2*)(outp + (((size_t)((b * 128 + y) * 128 + x)) << 6));
#pragma unroll
            for (int nt = 0; nt < 2; ++nt) {
                int o = nwarp * 16 + nt * 8 + (lane & 3) * 2;
                rowp[o >> 1] = __floats2half2_rn(acc[mt][nt][half * 2], acc[mt][nt][half * 2 + 1]);
            }
        }
    }
}

// ---------------- fused attn: 4 px/warp; writes NCHW fp32 directly via smem stage ----------------
__global__ void __launch_bounds__(256) fused_attn(
    const __half* __restrict__ gH, const __half* __restrict__ cH,
    const __half* __restrict__ nbh_h, const float* __restrict__ mv,
    const float* __restrict__ b1, const __half* __restrict__ w2h,
    const float* __restrict__ b2, float* __restrict__ out)
{
    __shared__ float sout[32][65];   // [local px][channel], pad 65 -> conflict-free column reads

    int wg = blockIdx.x * 8 + (threadIdx.x >> 5);
    int lane = threadIdx.x & 31;
    int grp = lane >> 3;          // pixel within warp
    int lg = lane & 7;            // lane within pixel group; channels lg*8..lg*8+7
    int pxl = ((threadIdx.x >> 5) << 2) | grp;   // local pixel 0..31
    int pixg = wg * 4 + grp;
    int b = pixg >> 14;
    int pix = pixg & (HWS - 1);
    int y = pix >> 7, x = pix & 127;

    float mvx = mv[(b*2 + 0)*HWS + pix];
    float mvy = mv[(b*2 + 1)*HWS + pix];
    const float inv = 2.0f / 127.0f;
    float gx = fminf(fmaxf(-1.0f + inv*(float)x + mvx*0.5f, -1.0f), 1.0f);
    float gy = fminf(fmaxf(-1.0f + inv*(float)y + mvy*0.5f, -1.0f), 1.0f);
    float px = (gx + 1.0f) * 0.5f * 127.0f;
    float py = (gy + 1.0f) * 0.5f * 127.0f;
    float fx0 = floorf(px), fy0 = floorf(py);
    float wx = px - fx0, wy = py - fy0;
    int ix0 = min(max((int)fx0, 0), WW - 1);
    int iy0 = min(max((int)fy0, 0), HH - 1);
    int ix1 = min(ix0 + 1, WW - 1);
    int iy1 = min(iy0 + 1, HH - 1);

    int pbase = b * HWS;
    const uint4* g4 = (const uint4*)gH;
    uint4 r00 = g4[(size_t)(pbase + iy0*WW + ix0)*8 + lg];
    uint4 r01 = g4[(size_t)(pbase + iy0*WW + ix1)*8 + lg];
    uint4 r10 = g4[(size_t)(pbase + iy1*WW + ix0)*8 + lg];
    uint4 r11 = g4[(size_t)(pbase + iy1*WW + ix1)*8 + lg];
    uint4 rcn = ((const uint4*)cH)[(size_t)(pbase + pix)*8 + lg];
    float w00 = (1.f-wx)*(1.f-wy), w01 = wx*(1.f-wy), w10 = (1.f-wx)*wy, w11 = wx*wy;

    float f00[8], f01[8], f10[8], f11[8], fcn[8];
    h8_to_f(r00, f00); h8_to_f(r01, f01); h8_to_f(r10, f10); h8_to_f(r11, f11);
    h8_to_f(rcn, fcn);
    float4 b1a = ((const float4*)b1)[lg*2];
    float4 b1b = ((const float4*)b1)[lg*2 + 1];
    float b1v[8] = {b1a.x, b1a.y, b1a.z, b1a.w, b1b.x, b1b.y, b1b.z, b1b.w};

    float h1[8];
#pragma unroll
    for (int i = 0; i < 8; ++i) {
        float v = f00[i]*w00 + f01[i]*w01 + f10[i]*w10 + f11[i]*w11 + fcn[i] + b1v[i];
        h1[i] = v >= 0.f ? v : 0.1f*v;
    }

    float part[9];
    const uint4* w24 = (const uint4*)w2h;
#pragma unroll
    for (int j = 0; j < 9; ++j) {
        float wv[8];
        h8_to_f(w24[j*8 + lg], wv);
        part[j] = h1[0]*wv[0] + h1[1]*wv[1] + h1[2]*wv[2] + h1[3]*wv[3]
                + h1[4]*wv[4] + h1[5]*wv[5] + h1[6]*wv[6] + h1[7]*wv[7];
    }
#pragma unroll
    for (int off = 1; off < 8; off <<= 1)
#pragma unroll
        for (int j = 0; j < 9; ++j)
            part[j] += __shfl_xor_sync(0xffffffffu, part[j], off);

    float mx = -1e30f;
#pragma unroll
    for (int j = 0; j < 9; ++j) { part[j] += b2[j]; mx = fmaxf(mx, part[j]); }
    float s = 0.f;
    float attn[9];
#pragma unroll
    for (int j = 0; j < 9; ++j) { attn[j] = __expf(part[j] - mx); s += attn[j]; }
    float sc = 1.0f / (9.0f * s);
#pragma unroll
    for (int j = 0; j < 9; ++j) attn[j] *= sc;

    float wyv[2] = {1.f - wy, wy};
    float wxv[2] = {1.f - wx, wx};
    int d1y = iy1 - iy0;
    int d1x = ix1 - ix0;
    float Wrow[3][4], Wcol[3][4];
#pragma unroll
    for (int dy = 0; dy < 3; ++dy)
#pragma unroll
        for (int r = 0; r < 4; ++r) { Wrow[dy][r] = 0.f; Wcol[dy][r] = 0.f; }
#pragma unroll
    for (int dy = 0; dy < 3; ++dy) {
        int rowlo = iy0 + dy - 1;
        float vlo = (rowlo >= 0 && rowlo < HH) ? wyv[0] : 0.f;
        Wrow[dy][dy] += vlo;
        int rowhi = iy1 + dy - 1;
        float vhi = (rowhi >= 0 && rowhi < HH) ? wyv[1] : 0.f;
        if (d1y) Wrow[dy][dy+1] += vhi; else Wrow[dy][dy] += vhi;

        int collo = ix0 + dy - 1;
        float ulo = (collo >= 0 && collo < WW) ? wxv[0] : 0.f;
        Wcol[dy][dy] += ulo;
        int colhi = ix1 + dy - 1;
        float uhi = (colhi >= 0 && colhi < WW) ? wxv[1] : 0.f;
        if (d1x) Wcol[dy][dy+1] += uhi; else Wcol[dy][dy] += uhi;
    }
    float tmp[3][4];
#pragma unroll
    for (int dy = 0; dy < 3; ++dy)
#pragma unroll
        for (int sx = 0; sx < 4; ++sx) {
            float t = 0.f;
#pragma unroll
            for (int dx = 0; dx < 3; ++dx) t += attn[dy*3 + dx] * Wcol[dx][sx];
            tmp[dy][sx] = t;
        }
    float coeff[16];
#pragma unroll
    for (int r = 0; r < 4; ++r)
#pragma unroll
        for (int sx = 0; sx < 4; ++sx) {
            float t = 0.f;
#pragma unroll
            for (int dy = 0; dy < 3; ++dy) t += Wrow[dy][r] * tmp[dy][sx];
            coeff[r*4 + sx] = t;
        }

    int rowi[4], coli[4];
#pragma unroll
    for (int r = 0; r < 4; ++r) rowi[r] = min(max(iy0 - 1 + r, 0), HH - 1);
#pragma unroll
    for (int sx = 0; sx < 4; ++sx) coli[sx] = min(max(ix0 - 1 + sx, 0), WW - 1);

    const uint4* n4 = (const uint4*)nbh_h;
    float o[8];
#pragma unroll
    for (int i = 0; i < 8; ++i) o[i] = 0.f;
#pragma unroll
    for (int r = 0; r < 4; ++r) {
        size_t rb = (size_t)(pbase + rowi[r]*WW)*8 + lg;
#pragma unroll
        for (int sx = 0; sx < 4; ++sx) {
            uint4 v = n4[rb + (size_t)coli[sx]*8];
            float fv[8];
            h8_to_f(v, fv);
            float cf = coeff[r*4 + sx];
#pragma unroll
            for (int i = 0; i < 8; ++i) o[i] += cf * fv[i];
        }
    }

    // stage to smem, then write NCHW coalesced (32-px contiguous rows per channel)
#pragma unroll
    for (int i = 0; i < 8; ++i)
        sout[pxl][lg*8 + i] = o[i];
    __syncthreads();

    int pix0 = (blockIdx.x * 32) & (HWS - 1);      // block's first pixel within batch
    int px2 = threadIdx.x & 31;
    int cb = (threadIdx.x >> 5) * 8;
    float* ob = out + (size_t)b * 64 * HWS + pix0 + px2;
#pragma unroll
    for (int i = 0; i < 8; ++i)
        ob[(size_t)(cb + i) * HWS] = sout[px2][cb + i];
}

// ---------------- launcher ----------------
extern "C" void kernel_launch(void* const* d_in, const int* in_sizes, int n_in,
                              void* d_out, int out_size)
{
    const float* nbh = (const float*)d_in[0];
    const float* cen = (const float*)d_in[1];
    const float* mv  = (const float*)d_in[2];
    const float* w1  = (const float*)d_in[3];
    const float* b1  = (const float*)d_in[4];
    const float* w2  = (const float*)d_in[5];
    const float* b2  = (const float*)d_in[6];
    float* out = (float*)d_out;

    __half *nh, *ch, *gH, *cH, *wc, *w2h;
    cudaGetSymbolAddress((void**)&nh,   d_nbh_h);
    cudaGetSymbolAddress((void**)&ch,   d_cen_h);
    cudaGetSymbolAddress((void**)&gH,   d_gH);
    cudaGetSymbolAddress((void**)&cH,   d_cH);
    cudaGetSymbolAddress((void**)&wc,   d_wcomb);
    cudaGetSymbolAddress((void**)&w2h,  d_w2h);

    cudaFuncSetAttribute(conv_tc, cudaFuncAttributeMaxDynamicSharedMemorySize, CONV_SMEM);

    prep_w<<<(2*9*4096 + 9*CHC + 255)/256, 256>>>(w1, w2, wc, w2h);

    // NCHW -> NHWC fp16 for both inputs in one launch
    transpose_split2<<<dim3(HWS/32, CHC/32, 2*BB), dim3(32, 8)>>>(nbh, cen, nh, ch);

    // HMMA dual conv: grid (2-row tile, batch, conv)
    conv_tc<<<dim3(HH/2, BB, 2), 512, CONV_SMEM>>>(nh, ch, wc, gH, cH);

    // 4 px/warp, 8 warps/block -> 32 px/block; writes NCHW directly
    fused_attn<<<BB*HWS/32, 256>>>(gH, cH, nh, mv, b1, w2h, b2, out);
}

// round 9
// speedup vs baseline: 4.9534x; 1.0324x over previous
#include <cuda_runtime.h>
#include <cuda_fp16.h>
#include <cstdint>

#define BB 4
#define CHC 64
#define HH 128
#define WW 128
#define HWS (HH*WW)

// ---------------- scratch (no allocations allowed) ----------------
__device__ __align__(256) __half d_nbh_h[BB*HWS*CHC];      // NHWC fp16
__device__ __align__(256) __half d_cen_h[BB*HWS*CHC];
__device__ __align__(256) __half d_gH[BB*HWS*CHC];         // conv(nbh) NHWC fp16
__device__ __align__(256) __half d_cH[BB*HWS*CHC];         // conv(cen) NHWC fp16
__device__ __align__(256) __half d_wcomb[2*9*CHC*CHC];     // [conv][tap][o][c] fp16
__device__ __align__(256) __half d_w2h[9*CHC];             // w2 fp16

// ---------------- PTX helpers (portable sm_80+ subset only) ----------------
__device__ __forceinline__ uint32_t smem_u32(const void* p) {
    uint32_t a;
    asm("{ .reg .u64 t; cvta.to.shared.u64 t, %1; cvt.u32.u64 %0, t; }" : "=r"(a) : "l"(p));
    return a;
}
__device__ __forceinline__ void cpa16(uint32_t dst, const void* src) {
    asm volatile("cp.async.cg.shared.global [%0], [%1], 16;" :: "r"(dst), "l"(src));
}
__device__ __forceinline__ void ldsm4(uint32_t* r, uint32_t addr) {
    asm volatile("ldmatrix.sync.aligned.m8n8.x4.shared.b16 {%0,%1,%2,%3}, [%4];"
        : "=r"(r[0]), "=r"(r[1]), "=r"(r[2]), "=r"(r[3]) : "r"(addr));
}
__device__ __forceinline__ void mma_fp16(float* d, const uint32_t* a, const uint32_t* b) {
    asm volatile("mma.sync.aligned.m16n8k16.row.col.f32.f16.f16.f32 "
        "{%0,%1,%2,%3}, {%4,%5,%6,%7}, {%8,%9}, {%0,%1,%2,%3};"
        : "+f"(d[0]), "+f"(d[1]), "+f"(d[2]), "+f"(d[3])
        : "r"(a[0]), "r"(a[1]), "r"(a[2]), "r"(a[3]), "r"(b[0]), "r"(b[1]));
}
__device__ __forceinline__ void h8_to_f(const uint4& u, float* f) {
    const __half2* h = (const __half2*)&u;
    float2 t;
    t = __half22float2(h[0]); f[0] = t.x; f[1] = t.y;
    t = __half22float2(h[1]); f[2] = t.x; f[3] = t.y;
    t = __half22float2(h[2]); f[4] = t.x; f[5] = t.y;
    t = __half22float2(h[3]); f[6] = t.x; f[7] = t.y;
}

// ---------------- transpose NCHW->NHWC for both inputs (fp16 cast) ----------------
__global__ void transpose_split2(const float* __restrict__ nbh, const float* __restrict__ cen,
                                 __half* __restrict__ nh, __half* __restrict__ ch)
{
    __shared__ float tile[32][33];
    int which = blockIdx.z >> 2;
    int b = blockIdx.z & 3;
    const float* in = which ? cen : nbh;
    __half* oh = which ? ch : nh;
    const float* inb = in + (size_t)b * CHC * HWS;
    int c0 = blockIdx.x * 32;
    int r0 = blockIdx.y * 32;
#pragma unroll
    for (int i = 0; i < 32; i += 8)
        tile[threadIdx.y + i][threadIdx.x] =
            inb[(size_t)(r0 + threadIdx.y + i) * HWS + (c0 + threadIdx.x)];
    __syncthreads();
#pragma unroll
    for (int i = 0; i < 32; i += 8) {
        float v = tile[threadIdx.x][threadIdx.y + i];
        int px = c0 + threadIdx.y + i;
        int chn = r0 + threadIdx.x;
        oh[((size_t)b * HWS + px) * 64 + chn] = __float2half(v);
    }
}

// ---------------- weight prep: conv weights + w2 -> fp16 ----------------
__global__ void prep_w(const float* __restrict__ w1, const float* __restrict__ w2,
                       __half* __restrict__ wcomb, __half* __restrict__ w2h)
{
    int idx = blockIdx.x * 256 + threadIdx.x;
    if (idx < 2*9*4096) {
        int c = idx & 63;
        int o = (idx >> 6) & 63;
        int tap = (idx >> 12) % 9;
        int conv = idx / (9 * 4096);
        wcomb[idx] = __float2half(w1[o * 1152 + conv * 576 + c * 9 + tap]);
    } else {
        int k = idx - 2*9*4096;
        if (k < 9*CHC) w2h[k] = __float2half(w2[k]);
    }
}

// ---------------- HMMA dual conv3x3, single-pass fp16, fp16 output ----------------
#define A_BYTES (520*128)
#define W_OFF   A_BYTES
#define CONV_SMEM (A_BYTES + 9*64*128)

__global__ void __launch_bounds__(512, 1) conv_tc(
    const __half* __restrict__ nbh_h,
    const __half* __restrict__ cen_h,
    const __half* __restrict__ wcomb,
    __half* __restrict__ gH, __half* __restrict__ cH)
{
    extern __shared__ char smem[];
    const int tid = threadIdx.x;
    const int lane = tid & 31;
    const int wid = tid >> 5;
    const int mwarp = wid >> 2, nwarp = wid & 3;
    const int y0 = blockIdx.x * 2;
    const int b = blockIdx.y;
    const int conv = blockIdx.z;
    const __half* src = conv ? cen_h : nbh_h;
    __half* outp = conv ? cH : gH;
    const __half* wsrc = wcomb + (size_t)conv * 9 * 4096;
    const uint32_t sb = smem_u32(smem);

#pragma unroll
    for (int it = 0; it < 8; ++it) {
        int i = tid + it * 512;
        int px = i >> 3, chn = i & 7;
        int ry = px >> 7, x = px & 127;
        int yy = y0 - 1 + ry;
        int pxb = ry * 130 + x + 1;
        uint32_t off = (uint32_t)pxb * 128 + (((uint32_t)chn ^ (pxb & 7)) << 4);
        if ((unsigned)yy < 128u)
            cpa16(sb + off, src + (((size_t)((b * 128 + yy) * 128 + x)) << 6) + chn * 8);
        else
            *(uint4*)(smem + off) = make_uint4(0u, 0u, 0u, 0u);
    }
    if (tid < 64) {
        int pp = tid >> 3;
        int ry = pp >> 1;
        int xpad = (pp & 1) ? 129 : 0;
        int pxb = ry * 130 + xpad;
        int chn = tid & 7;
        uint32_t off = (uint32_t)pxb * 128 + (((uint32_t)chn ^ (pxb & 7)) << 4);
        *(uint4*)(smem + off) = make_uint4(0u, 0u, 0u, 0u);
    }
#pragma unroll
    for (int it = 0; it < 9; ++it) {
        int i = tid + it * 512;
        int row = i >> 3, chn = i & 7;
        uint32_t off = W_OFF + (uint32_t)row * 128 + (((uint32_t)chn ^ (row & 7)) << 4);
        cpa16(sb + off, wsrc + row * 64 + chn * 8);
    }
    asm volatile("cp.async.commit_group;");
    asm volatile("cp.async.wait_group 0;");
    __syncthreads();

    float acc[4][2][4];
#pragma unroll
    for (int mt = 0; mt < 4; ++mt)
#pragma unroll
        for (int nt = 0; nt < 2; ++nt)
#pragma unroll
            for (int q = 0; q < 4; ++q) acc[mt][nt][q] = 0.f;

    const int chalfA = lane >> 4;
    const int chalfB = (lane >> 3) & 1;
    const int o_ld = nwarp * 16 + (lane & 7) + ((lane >> 4) << 3);
    const uint32_t bsw = ((uint32_t)(o_ld & 7)) << 4;
    const uint32_t browb = sb + W_OFF + (uint32_t)o_ld * 128;

    int mbase[4], mx[4];
#pragma unroll
    for (int mt = 0; mt < 4; ++mt) {
        int m = mwarp * 64 + mt * 16 + (lane & 15);
        mbase[mt] = (m >> 7);
        mx[mt] = m & 127;
    }

#pragma unroll
    for (int t = 0; t < 9; ++t) {
        const int dy = t / 3 - 1, dx = t % 3 - 1;
        uint32_t arow[4], asw[4];
#pragma unroll
        for (int mt = 0; mt < 4; ++mt) {
            int pxb = (mbase[mt] + dy + 1) * 130 + (mx[mt] + dx + 1);
            arow[mt] = sb + (uint32_t)pxb * 128;
            asw[mt] = ((uint32_t)(pxb & 7)) << 4;
        }
        const uint32_t brow = browb + (uint32_t)t * 64 * 128;

#pragma unroll
        for (int ks = 0; ks < 4; ++ks) {
            const uint32_t chi = (uint32_t)(ks * 2 + chalfA) << 4;
            uint32_t a[4][4];
#pragma unroll
            for (int mt = 0; mt < 4; ++mt)
                ldsm4(a[mt], arow[mt] + (chi ^ asw[mt]));
            const uint32_t cbi = (uint32_t)(ks * 2 + chalfB) << 4;
            uint32_t bv[4];
            ldsm4(bv, brow + (cbi ^ bsw));
#pragma unroll
            for (int mt = 0; mt < 4; ++mt)
#pragma unroll
                for (int nt = 0; nt < 2; ++nt)
                    mma_fp16(acc[mt][nt], a[mt], &bv[nt * 2]);
        }
    }

#pragma unroll
    for (int mt = 0; mt < 4; ++mt) {
        int m0 = mwarp * 64 + mt * 16 + (lane >> 2);
#pragma unroll
        for (int half = 0; half < 2; ++half) {
            int m = m0 + half * 8;
            int y = y0 + (m >> 7), x = m & 127;
            __half2* rowp = (__half2*)(outp + (((size_t)((b * 128 + y) * 128 + x)) << 6));
#pragma unroll
            for (int nt = 0; nt < 2; ++nt) {
                int o = nwarp * 16 + nt * 8 + (lane & 3) * 2;
                rowp[o >> 1] = __floats2half2_rn(acc[mt][nt][half * 2], acc[mt][nt][half * 2 + 1]);
            }
        }
    }
}

// ---------------- fused attn: 4 px/warp; half2 gather; writes NCHW fp32 via smem ----------------
__global__ void __launch_bounds__(256) fused_attn(
    const __half* __restrict__ gH, const __half* __restrict__ cH,
    const __half* __restrict__ nbh_h, const float* __restrict__ mv,
    const float* __restrict__ b1, const __half* __restrict__ w2h,
    const float* __restrict__ b2, float* __restrict__ out)
{
    __shared__ float sout[32][65];   // [local px][channel]

    int wg = blockIdx.x * 8 + (threadIdx.x >> 5);
    int lane = threadIdx.x & 31;
    int grp = lane >> 3;          // pixel within warp
    int lg = lane & 7;            // lane within pixel group; channels lg*8..lg*8+7
    int pxl = ((threadIdx.x >> 5) << 2) | grp;   // local pixel 0..31
    int pixg = wg * 4 + grp;
    int b = pixg >> 14;
    int pix = pixg & (HWS - 1);
    int y = pix >> 7, x = pix & 127;

    float mvx = mv[(b*2 + 0)*HWS + pix];
    float mvy = mv[(b*2 + 1)*HWS + pix];
    const float inv = 2.0f / 127.0f;
    float gx = fminf(fmaxf(-1.0f + inv*(float)x + mvx*0.5f, -1.0f), 1.0f);
    float gy = fminf(fmaxf(-1.0f + inv*(float)y + mvy*0.5f, -1.0f), 1.0f);
    float px = (gx + 1.0f) * 0.5f * 127.0f;
    float py = (gy + 1.0f) * 0.5f * 127.0f;
    float fx0 = floorf(px), fy0 = floorf(py);
    float wx = px - fx0, wy = py - fy0;
    int ix0 = min(max((int)fx0, 0), WW - 1);
    int iy0 = min(max((int)fy0, 0), HH - 1);
    int ix1 = min(ix0 + 1, WW - 1);
    int iy1 = min(iy0 + 1, HH - 1);

    int pbase = b * HWS;
    const uint4* g4 = (const uint4*)gH;
    uint4 r00 = g4[(size_t)(pbase + iy0*WW + ix0)*8 + lg];
    uint4 r01 = g4[(size_t)(pbase + iy0*WW + ix1)*8 + lg];
    uint4 r10 = g4[(size_t)(pbase + iy1*WW + ix0)*8 + lg];
    uint4 r11 = g4[(size_t)(pbase + iy1*WW + ix1)*8 + lg];
    uint4 rcn = ((const uint4*)cH)[(size_t)(pbase + pix)*8 + lg];
    float w00 = (1.f-wx)*(1.f-wy), w01 = wx*(1.f-wy), w10 = (1.f-wx)*wy, w11 = wx*wy;

    float f00[8], f01[8], f10[8], f11[8], fcn[8];
    h8_to_f(r00, f00); h8_to_f(r01, f01); h8_to_f(r10, f10); h8_to_f(r11, f11);
    h8_to_f(rcn, fcn);
    float4 b1a = ((const float4*)b1)[lg*2];
    float4 b1b = ((const float4*)b1)[lg*2 + 1];
    float b1v[8] = {b1a.x, b1a.y, b1a.z, b1a.w, b1b.x, b1b.y, b1b.z, b1b.w};

    float h1[8];
#pragma unroll
    for (int i = 0; i < 8; ++i) {
        float v = f00[i]*w00 + f01[i]*w01 + f10[i]*w10 + f11[i]*w11 + fcn[i] + b1v[i];
        h1[i] = v >= 0.f ? v : 0.1f*v;
    }

    float part[9];
    const uint4* w24 = (const uint4*)w2h;
#pragma unroll
    for (int j = 0; j < 9; ++j) {
        float wv[8];
        h8_to_f(w24[j*8 + lg], wv);
        part[j] = h1[0]*wv[0] + h1[1]*wv[1] + h1[2]*wv[2] + h1[3]*wv[3]
                + h1[4]*wv[4] + h1[5]*wv[5] + h1[6]*wv[6] + h1[7]*wv[7];
    }
#pragma unroll
    for (int off = 1; off < 8; off <<= 1)
#pragma unroll
        for (int j = 0; j < 9; ++j)
            part[j] += __shfl_xor_sync(0xffffffffu, part[j], off);

    float mx = -1e30f;
#pragma unroll
    for (int j = 0; j < 9; ++j) { part[j] += b2[j]; mx = fmaxf(mx, part[j]); }
    float s = 0.f;
    float attn[9];
#pragma unroll
    for (int j = 0; j < 9; ++j) { attn[j] = __expf(part[j] - mx); s += attn[j]; }
    float sc = 1.0f / (9.0f * s);
#pragma unroll
    for (int j = 0; j < 9; ++j) attn[j] *= sc;

    float wyv[2] = {1.f - wy, wy};
    float wxv[2] = {1.f - wx, wx};
    int d1y = iy1 - iy0;
    int d1x = ix1 - ix0;
    float Wrow[3][4], Wcol[3][4];
#pragma unroll
    for (int dy = 0; dy < 3; ++dy)
#pragma unroll
        for (int r = 0; r < 4; ++r) { Wrow[dy][r] = 0.f; Wcol[dy][r] = 0.f; }
#pragma unroll
    for (int dy = 0; dy < 3; ++dy) {
        int rowlo = iy0 + dy - 1;
        float vlo = (rowlo >= 0 && rowlo < HH) ? wyv[0] : 0.f;
        Wrow[dy][dy] += vlo;
        int rowhi = iy1 + dy - 1;
        float vhi = (rowhi >= 0 && rowhi < HH) ? wyv[1] : 0.f;
        if (d1y) Wrow[dy][dy+1] += vhi; else Wrow[dy][dy] += vhi;

        int collo = ix0 + dy - 1;
        float ulo = (collo >= 0 && collo < WW) ? wxv[0] : 0.f;
        Wcol[dy][dy] += ulo;
        int colhi = ix1 + dy - 1;
        float uhi = (colhi >= 0 && colhi < WW) ? wxv[1] : 0.f;
        if (d1x) Wcol[dy][dy+1] += uhi; else Wcol[dy][dy] += uhi;
    }
    float tmp[3][4];
#pragma unroll
    for (int dy = 0; dy < 3; ++dy)
#pragma unroll
        for (int sx = 0; sx < 4; ++sx) {
            float t = 0.f;
#pragma unroll
            for (int dx = 0; dx < 3; ++dx) t += attn[dy*3 + dx] * Wcol[dx][sx];
            tmp[dy][sx] = t;
        }
    float coeff[16];
#pragma unroll
    for (int r = 0; r < 4; ++r)
#pragma unroll
        for (int sx = 0; sx < 4; ++sx) {
            float t = 0.f;
#pragma unroll
            for (int dy = 0; dy < 3; ++dy) t += Wrow[dy][r] * tmp[dy][sx];
            coeff[r*4 + sx] = t;
        }

    int rowi[4], coli[4];
#pragma unroll
    for (int r = 0; r < 4; ++r) rowi[r] = min(max(iy0 - 1 + r, 0), HH - 1);
#pragma unroll
    for (int sx = 0; sx < 4; ++sx) coli[sx] = min(max(ix0 - 1 + sx, 0), WW - 1);

    // gather in half2 FMA; two accumulator sets (rows 0-1, rows 2-3), merged in fp32
    const uint4* n4 = (const uint4*)nbh_h;
    __half2 accA[4], accB[4];
    const __half2 hz = __float2half2_rn(0.f);
#pragma unroll
    for (int q = 0; q < 4; ++q) { accA[q] = hz; accB[q] = hz; }
#pragma unroll
    for (int r = 0; r < 4; ++r) {
        size_t rb = (size_t)(pbase + rowi[r]*WW)*8 + lg;
#pragma unroll
        for (int sx = 0; sx < 4; ++sx) {
            uint4 v = n4[rb + (size_t)coli[sx]*8];
            __half2 cfh = __float2half2_rn(coeff[r*4 + sx]);
            const __half2* hv = (const __half2*)&v;
#pragma unroll
            for (int q = 0; q < 4; ++q) {
                if (r < 2) accA[q] = __hfma2(hv[q], cfh, accA[q]);
                else       accB[q] = __hfma2(hv[q], cfh, accB[q]);
            }
        }
    }
    float o[8];
#pragma unroll
    for (int q = 0; q < 4; ++q) {
        float2 fa = __half22float2(accA[q]);
        float2 fb = __half22float2(accB[q]);
        o[2*q]   = fa.x + fb.x;
        o[2*q+1] = fa.y + fb.y;
    }

    // stage to smem, then write NCHW coalesced (32-px contiguous rows per channel)
#pragma unroll
    for (int i = 0; i < 8; ++i)
        sout[pxl][lg*8 + i] = o[i];
    __syncthreads();

    int pix0 = (blockIdx.x * 32) & (HWS - 1);
    int px2 = threadIdx.x & 31;
    int cb = (threadIdx.x >> 5) * 8;
    float* ob = out + (size_t)b * 64 * HWS + pix0 + px2;
#pragma unroll
    for (int i = 0; i < 8; ++i)
        ob[(size_t)(cb + i) * HWS] = sout[px2][cb + i];
}

// ---------------- launcher ----------------
extern "C" void kernel_launch(void* const* d_in, const int* in_sizes, int n_in,
                              void* d_out, int out_size)
{
    const float* nbh = (const float*)d_in[0];
    const float* cen = (const float*)d_in[1];
    const float* mv  = (const float*)d_in[2];
    const float* w1  = (const float*)d_in[3];
    const float* b1  = (const float*)d_in[4];
    const float* w2  = (const float*)d_in[5];
    const float* b2  = (const float*)d_in[6];
    float* out = (float*)d_out;

    __half *nh, *ch, *gH, *cH, *wc, *w2h;
    cudaGetSymbolAddress((void**)&nh,   d_nbh_h);
    cudaGetSymbolAddress((void**)&ch,   d_cen_h);
    cudaGetSymbolAddress((void**)&gH,   d_gH);
    cudaGetSymbolAddress((void**)&cH,   d_cH);
    cudaGetSymbolAddress((void**)&wc,   d_wcomb);
    cudaGetSymbolAddress((void**)&w2h,  d_w2h);

    cudaFuncSetAttribute(conv_tc, cudaFuncAttributeMaxDynamicSharedMemorySize, CONV_SMEM);

    prep_w<<<(2*9*4096 + 9*CHC + 255)/256, 256>>>(w1, w2, wc, w2h);

    // NCHW -> NHWC fp16 for both inputs in one launch
    transpose_split2<<<dim3(HWS/32, CHC/32, 2*BB), dim3(32, 8)>>>(nbh, cen, nh, ch);

    // HMMA dual conv: grid (2-row tile, batch, conv)
    conv_tc<<<dim3(HH/2, BB, 2), 512, CONV_SMEM>>>(nh, ch, wc, gH, cH);

    // 4 px/warp, 8 warps/block -> 32 px/block; writes NCHW directly
    fused_attn<<<BB*HWS/32, 256>>>(gH, cH, nh, mv, b1, w2h, b2, out);
}

// round 10
// speedup vs baseline: 5.2608x; 1.0620x over previous
#include <cuda_runtime.h>
#include <cuda_fp16.h>
#include <cstdint>

#define BB 4
#define CHC 64
#define HH 128
#define WW 128
#define HWS (HH*WW)

// ---------------- scratch (no allocations allowed) ----------------
__device__ __align__(256) __half d_nbh_h[BB*HWS*CHC];      // NHWC fp16
__device__ __align__(256) __half d_cen_h[BB*HWS*CHC];
__device__ __align__(256) __half d_gH[BB*HWS*CHC];         // conv(nbh) NHWC fp16
__device__ __align__(256) __half d_cH[BB*HWS*CHC];         // conv(cen) NHWC fp16
__device__ __align__(256) __half d_wcomb[2*9*CHC*CHC];     // [conv][tap][o][c] fp16
__device__ __align__(256) __half d_w2h[9*CHC];             // w2 fp16

// ---------------- PTX helpers (portable sm_80+ subset only) ----------------
__device__ __forceinline__ uint32_t smem_u32(const void* p) {
    uint32_t a;
    asm("{ .reg .u64 t; cvta.to.shared.u64 t, %1; cvt.u32.u64 %0, t; }" : "=r"(a) : "l"(p));
    return a;
}
__device__ __forceinline__ void cpa16(uint32_t dst, const void* src) {
    asm volatile("cp.async.cg.shared.global [%0], [%1], 16;" :: "r"(dst), "l"(src));
}
__device__ __forceinline__ void ldsm4(uint32_t* r, uint32_t addr) {
    asm volatile("ldmatrix.sync.aligned.m8n8.x4.shared.b16 {%0,%1,%2,%3}, [%4];"
        : "=r"(r[0]), "=r"(r[1]), "=r"(r[2]), "=r"(r[3]) : "r"(addr));
}
__device__ __forceinline__ void mma_fp16(float* d, const uint32_t* a, const uint32_t* b) {
    asm volatile("mma.sync.aligned.m16n8k16.row.col.f32.f16.f16.f32 "
        "{%0,%1,%2,%3}, {%4,%5,%6,%7}, {%8,%9}, {%0,%1,%2,%3};"
        : "+f"(d[0]), "+f"(d[1]), "+f"(d[2]), "+f"(d[3])
        : "r"(a[0]), "r"(a[1]), "r"(a[2]), "r"(a[3]), "r"(b[0]), "r"(b[1]));
}
__device__ __forceinline__ void h8_to_f(const uint4& u, float* f) {
    const __half2* h = (const __half2*)&u;
    float2 t;
    t = __half22float2(h[0]); f[0] = t.x; f[1] = t.y;
    t = __half22float2(h[1]); f[2] = t.x; f[3] = t.y;
    t = __half22float2(h[2]); f[4] = t.x; f[5] = t.y;
    t = __half22float2(h[3]); f[6] = t.x; f[7] = t.y;
}

// ---------------- transpose NCHW->NHWC (fp16) + weight prep, one launch ----------------
// grid.z: 0..7 -> transpose (which*4+b); 8 -> weight conversion
__global__ void transpose_prep(const float* __restrict__ nbh, const float* __restrict__ cen,
                               __half* __restrict__ nh, __half* __restrict__ ch,
                               const float* __restrict__ w1, const float* __restrict__ w2,
                               __half* __restrict__ wcomb, __half* __restrict__ w2h)
{
    if (blockIdx.z == 8) {
        int idx = (blockIdx.y * gridDim.x + blockIdx.x) * 256 + threadIdx.y * 32 + threadIdx.x;
        if (idx < 2*9*4096) {
            int c = idx & 63;
            int o = (idx >> 6) & 63;
            int tap = (idx >> 12) % 9;
            int conv = idx / (9 * 4096);
            wcomb[idx] = __float2half(w1[o * 1152 + conv * 576 + c * 9 + tap]);
        } else if (idx < 2*9*4096 + 9*CHC) {
            int k = idx - 2*9*4096;
            w2h[k] = __float2half(w2[k]);
        }
        return;
    }
    __shared__ float tile[32][33];
    int which = blockIdx.z >> 2;
    int b = blockIdx.z & 3;
    const float* in = which ? cen : nbh;
    __half* oh = which ? ch : nh;
    const float* inb = in + (size_t)b * CHC * HWS;
    int c0 = blockIdx.x * 32;
    int r0 = blockIdx.y * 32;
#pragma unroll
    for (int i = 0; i < 32; i += 8)
        tile[threadIdx.y + i][threadIdx.x] =
            inb[(size_t)(r0 + threadIdx.y + i) * HWS + (c0 + threadIdx.x)];
    __syncthreads();
#pragma unroll
    for (int i = 0; i < 32; i += 8) {
        float v = tile[threadIdx.x][threadIdx.y + i];
        int px = c0 + threadIdx.y + i;
        int chn = r0 + threadIdx.x;
        oh[((size_t)b * HWS + px) * 64 + chn] = __float2half(v);
    }
}

// ---------------- HMMA dual conv3x3, single-pass fp16 ----------------
// 8 warps, warp tile M64xN32 (4x2 warp grid) -> A ldsm redundancy 2x (was 4x),
// crossbar 24.6KB/k-step vs 40KB at 16 warps.
#define A_BYTES (520*128)
#define W_OFF   A_BYTES
#define CONV_SMEM (A_BYTES + 9*64*128)

__global__ void __launch_bounds__(256, 1) conv_tc(
    const __half* __restrict__ nbh_h,
    const __half* __restrict__ cen_h,
    const __half* __restrict__ wcomb,
    __half* __restrict__ gH, __half* __restrict__ cH)
{
    extern __shared__ char smem[];
    const int tid = threadIdx.x;
    const int lane = tid & 31;
    const int wid = tid >> 5;
    const int mwarp = wid >> 1, nwarp = wid & 1;
    const int y0 = blockIdx.x * 2;
    const int b = blockIdx.y;
    const int conv = blockIdx.z;
    const __half* src = conv ? cen_h : nbh_h;
    __half* outp = conv ? cH : gH;
    const __half* wsrc = wcomb + (size_t)conv * 9 * 4096;
    const uint32_t sb = smem_u32(smem);

    // ---- stage A: 512 px x 8 chunks of 16B, swizzled; OOB rows -> zeros ----
#pragma unroll
    for (int it = 0; it < 16; ++it) {
        int i = tid + it * 256;
        int px = i >> 3, chn = i & 7;
        int ry = px >> 7, x = px & 127;
        int yy = y0 - 1 + ry;
        int pxb = ry * 130 + x + 1;
        uint32_t off = (uint32_t)pxb * 128 + (((uint32_t)chn ^ (pxb & 7)) << 4);
        if ((unsigned)yy < 128u)
            cpa16(sb + off, src + (((size_t)((b * 128 + yy) * 128 + x)) << 6) + chn * 8);
        else
            *(uint4*)(smem + off) = make_uint4(0u, 0u, 0u, 0u);
    }
    if (tid < 64) {
        int pp = tid >> 3;
        int ry = pp >> 1;
        int xpad = (pp & 1) ? 129 : 0;
        int pxb = ry * 130 + xpad;
        int chn = tid & 7;
        uint32_t off = (uint32_t)pxb * 128 + (((uint32_t)chn ^ (pxb & 7)) << 4);
        *(uint4*)(smem + off) = make_uint4(0u, 0u, 0u, 0u);
    }
    // ---- stage all 9 taps of W: 576 o-rows x 8 chunks ----
#pragma unroll
    for (int it = 0; it < 18; ++it) {
        int i = tid + it * 256;
        int row = i >> 3, chn = i & 7;
        uint32_t off = W_OFF + (uint32_t)row * 128 + (((uint32_t)chn ^ (row & 7)) << 4);
        cpa16(sb + off, wsrc + row * 64 + chn * 8);
    }
    asm volatile("cp.async.commit_group;");
    asm volatile("cp.async.wait_group 0;");
    __syncthreads();

    float acc[4][4][4];
#pragma unroll
    for (int mt = 0; mt < 4; ++mt)
#pragma unroll
        for (int nt = 0; nt < 4; ++nt)
#pragma unroll
            for (int q = 0; q < 4; ++q) acc[mt][nt][q] = 0.f;

    const int chalfA = lane >> 4;
    const int chalfB = (lane >> 3) & 1;
    const int o_ld = nwarp * 32 + (lane & 7) + ((lane >> 4) << 3);
    const uint32_t bsw = ((uint32_t)(o_ld & 7)) << 4;
    const uint32_t browb = sb + W_OFF + (uint32_t)o_ld * 128;

    int mbase[4], mx[4];
#pragma unroll
    for (int mt = 0; mt < 4; ++mt) {
        int m = mwarp * 64 + mt * 16 + (lane & 15);
        mbase[mt] = (m >> 7);
        mx[mt] = m & 127;
    }

#pragma unroll
    for (int t = 0; t < 9; ++t) {
        const int dy = t / 3 - 1, dx = t % 3 - 1;
        uint32_t arow[4], asw[4];
#pragma unroll
        for (int mt = 0; mt < 4; ++mt) {
            int pxb = (mbase[mt] + dy + 1) * 130 + (mx[mt] + dx + 1);
            arow[mt] = sb + (uint32_t)pxb * 128;
            asw[mt] = ((uint32_t)(pxb & 7)) << 4;
        }
        const uint32_t brow0 = browb + (uint32_t)t * 64 * 128;
        const uint32_t brow1 = brow0 + 16 * 128;

#pragma unroll
        for (int ks = 0; ks < 4; ++ks) {
            const uint32_t chi = (uint32_t)(ks * 2 + chalfA) << 4;
            uint32_t a[4][4];
#pragma unroll
            for (int mt = 0; mt < 4; ++mt)
                ldsm4(a[mt], arow[mt] + (chi ^ asw[mt]));
            const uint32_t cbi = (uint32_t)(ks * 2 + chalfB) << 4;
            uint32_t bv0[4], bv1[4];
            ldsm4(bv0, brow0 + (cbi ^ bsw));
            ldsm4(bv1, brow1 + (cbi ^ bsw));
#pragma unroll
            for (int mt = 0; mt < 4; ++mt) {
                mma_fp16(acc[mt][0], a[mt], &bv0[0]);
                mma_fp16(acc[mt][1], a[mt], &bv0[2]);
                mma_fp16(acc[mt][2], a[mt], &bv1[0]);
                mma_fp16(acc[mt][3], a[mt], &bv1[2]);
            }
        }
    }

    // ---- epilogue: fragments -> NHWC fp16 ----
#pragma unroll
    for (int mt = 0; mt < 4; ++mt) {
        int m0 = mwarp * 64 + mt * 16 + (lane >> 2);
#pragma unroll
        for (int half = 0; half < 2; ++half) {
            int m = m0 + half * 8;
            int y = y0 + (m >> 7), x = m & 127;
            __half2* rowp = (__half2*)(outp + (((size_t)((b * 128 + y) * 128 + x)) << 6));
#pragma unroll
            for (int nt = 0; nt < 4; ++nt) {
                int o = nwarp * 32 + nt * 8 + (lane & 3) * 2;
                rowp[o >> 1] = __floats2half2_rn(acc[mt][nt][half * 2], acc[mt][nt][half * 2 + 1]);
            }
        }
    }
}

// ---------------- fused attn: 4 px/warp; fp32 gather; writes NCHW fp32 via smem ----------------
__global__ void __launch_bounds__(256) fused_attn(
    const __half* __restrict__ gH, const __half* __restrict__ cH,
    const __half* __restrict__ nbh_h, const float* __restrict__ mv,
    const float* __restrict__ b1, const __half* __restrict__ w2h,
    const float* __restrict__ b2, float* __restrict__ out)
{
    __shared__ float sout[32][65];   // [local px][channel]

    int wg = blockIdx.x * 8 + (threadIdx.x >> 5);
    int lane = threadIdx.x & 31;
    int grp = lane >> 3;          // pixel within warp
    int lg = lane & 7;            // lane within pixel group; channels lg*8..lg*8+7
    int pxl = ((threadIdx.x >> 5) << 2) | grp;   // local pixel 0..31
    int pixg = wg * 4 + grp;
    int b = pixg >> 14;
    int pix = pixg & (HWS - 1);
    int y = pix >> 7, x = pix & 127;

    float mvx = mv[(b*2 + 0)*HWS + pix];
    float mvy = mv[(b*2 + 1)*HWS + pix];
    const float inv = 2.0f / 127.0f;
    float gx = fminf(fmaxf(-1.0f + inv*(float)x + mvx*0.5f, -1.0f), 1.0f);
    float gy = fminf(fmaxf(-1.0f + inv*(float)y + mvy*0.5f, -1.0f), 1.0f);
    float px = (gx + 1.0f) * 0.5f * 127.0f;
    float py = (gy + 1.0f) * 0.5f * 127.0f;
    float fx0 = floorf(px), fy0 = floorf(py);
    float wx = px - fx0, wy = py - fy0;
    int ix0 = min(max((int)fx0, 0), WW - 1);
    int iy0 = min(max((int)fy0, 0), HH - 1);
    int ix1 = min(ix0 + 1, WW - 1);
    int iy1 = min(iy0 + 1, HH - 1);

    int pbase = b * HWS;
    const uint4* g4 = (const uint4*)gH;
    uint4 r00 = g4[(size_t)(pbase + iy0*WW + ix0)*8 + lg];
    uint4 r01 = g4[(size_t)(pbase + iy0*WW + ix1)*8 + lg];
    uint4 r10 = g4[(size_t)(pbase + iy1*WW + ix0)*8 + lg];
    uint4 r11 = g4[(size_t)(pbase + iy1*WW + ix1)*8 + lg];
    uint4 rcn = ((const uint4*)cH)[(size_t)(pbase + pix)*8 + lg];
    float w00 = (1.f-wx)*(1.f-wy), w01 = wx*(1.f-wy), w10 = (1.f-wx)*wy, w11 = wx*wy;

    float f00[8], f01[8], f10[8], f11[8], fcn[8];
    h8_to_f(r00, f00); h8_to_f(r01, f01); h8_to_f(r10, f10); h8_to_f(r11, f11);
    h8_to_f(rcn, fcn);
    float4 b1a = ((const float4*)b1)[lg*2];
    float4 b1b = ((const float4*)b1)[lg*2 + 1];
    float b1v[8] = {b1a.x, b1a.y, b1a.z, b1a.w, b1b.x, b1b.y, b1b.z, b1b.w};

    float h1[8];
#pragma unroll
    for (int i = 0; i < 8; ++i) {
        float v = f00[i]*w00 + f01[i]*w01 + f10[i]*w10 + f11[i]*w11 + fcn[i] + b1v[i];
        h1[i] = v >= 0.f ? v : 0.1f*v;
    }

    float part[9];
    const uint4* w24 = (const uint4*)w2h;
#pragma unroll
    for (int j = 0; j < 9; ++j) {
        float wv[8];
        h8_to_f(w24[j*8 + lg], wv);
        part[j] = h1[0]*wv[0] + h1[1]*wv[1] + h1[2]*wv[2] + h1[3]*wv[3]
                + h1[4]*wv[4] + h1[5]*wv[5] + h1[6]*wv[6] + h1[7]*wv[7];
    }
#pragma unroll
    for (int off = 1; off < 8; off <<= 1)
#pragma unroll
        for (int j = 0; j < 9; ++j)
            part[j] += __shfl_xor_sync(0xffffffffu, part[j], off);

    float mx = -1e30f;
#pragma unroll
    for (int j = 0; j < 9; ++j) { part[j] += b2[j]; mx = fmaxf(mx, part[j]); }
    float s = 0.f;
    float attn[9];
#pragma unroll
    for (int j = 0; j < 9; ++j) { attn[j] = __expf(part[j] - mx); s += attn[j]; }
    float sc = 1.0f / (9.0f * s);
#pragma unroll
    for (int j = 0; j < 9; ++j) attn[j] *= sc;

    float wyv[2] = {1.f - wy, wy};
    float wxv[2] = {1.f - wx, wx};
    int d1y = iy1 - iy0;
    int d1x = ix1 - ix0;
    float Wrow[3][4], Wcol[3][4];
#pragma unroll
    for (int dy = 0; dy < 3; ++dy)
#pragma unroll
        for (int r = 0; r < 4; ++r) { Wrow[dy][r] = 0.f; Wcol[dy][r] = 0.f; }
#pragma unroll
    for (int dy = 0; dy < 3; ++dy) {
        int rowlo = iy0 + dy - 1;
        float vlo = (rowlo >= 0 && rowlo < HH) ? wyv[0] : 0.f;
        Wrow[dy][dy] += vlo;
        int rowhi = iy1 + dy - 1;
        float vhi = (rowhi >= 0 && rowhi < HH) ? wyv[1] : 0.f;
        if (d1y) Wrow[dy][dy+1] += vhi; else Wrow[dy][dy] += vhi;

        int collo = ix0 + dy - 1;
        float ulo = (collo >= 0 && collo < WW) ? wxv[0] : 0.f;
        Wcol[dy][dy] += ulo;
        int colhi = ix1 + dy - 1;
        float uhi = (colhi >= 0 && colhi < WW) ? wxv[1] : 0.f;
        if (d1x) Wcol[dy][dy+1] += uhi; else Wcol[dy][dy] += uhi;
    }
    float tmp[3][4];
#pragma unroll
    for (int dy = 0; dy < 3; ++dy)
#pragma unroll
        for (int sx = 0; sx < 4; ++sx) {
            float t = 0.f;
#pragma unroll
            for (int dx = 0; dx < 3; ++dx) t += attn[dy*3 + dx] * Wcol[dx][sx];
            tmp[dy][sx] = t;
        }
    float coeff[16];
#pragma unroll
    for (int r = 0; r < 4; ++r)
#pragma unroll
        for (int sx = 0; sx < 4; ++sx) {
            float t = 0.f;
#pragma unroll
            for (int dy = 0; dy < 3; ++dy) t += Wrow[dy][r] * tmp[dy][sx];
            coeff[r*4 + sx] = t;
        }

    int rowi[4], coli[4];
#pragma unroll
    for (int r = 0; r < 4; ++r) rowi[r] = min(max(iy0 - 1 + r, 0), HH - 1);
#pragma unroll
    for (int sx = 0; sx < 4; ++sx) coli[sx] = min(max(ix0 - 1 + sx, 0), WW - 1);

    const uint4* n4 = (const uint4*)nbh_h;
    float o[8];
#pragma unroll
    for (int i = 0; i < 8; ++i) o[i] = 0.f;
#pragma unroll
    for (int r = 0; r < 4; ++r) {
        size_t rb = (size_t)(pbase + rowi[r]*WW)*8 + lg;
#pragma unroll
        for (int sx = 0; sx < 4; ++sx) {
            uint4 v = n4[rb + (size_t)coli[sx]*8];
            float fv[8];
            h8_to_f(v, fv);
            float cf = coeff[r*4 + sx];
#pragma unroll
            for (int i = 0; i < 8; ++i) o[i] += cf * fv[i];
        }
    }

    // stage to smem, then write NCHW coalesced (32-px contiguous rows per channel)
#pragma unroll
    for (int i = 0; i < 8; ++i)
        sout[pxl][lg*8 + i] = o[i];
    __syncthreads();

    int pix0 = (blockIdx.x * 32) & (HWS - 1);
    int px2 = threadIdx.x & 31;
    int cb = (threadIdx.x >> 5) * 8;
    float* ob = out + (size_t)b * 64 * HWS + pix0 + px2;
#pragma unroll
    for (int i = 0; i < 8; ++i)
        ob[(size_t)(cb + i) * HWS] = sout[px2][cb + i];
}

// ---------------- launcher ----------------
extern "C" void kernel_launch(void* const* d_in, const int* in_sizes, int n_in,
                              void* d_out, int out_size)
{
    const float* nbh = (const float*)d_in[0];
    const float* cen = (const float*)d_in[1];
    const float* mv  = (const float*)d_in[2];
    const float* w1  = (const float*)d_in[3];
    const float* b1  = (const float*)d_in[4];
    const float* w2  = (const float*)d_in[5];
    const float* b2  = (const float*)d_in[6];
    float* out = (float*)d_out;

    __half *nh, *ch, *gH, *cH, *wc, *w2h;
    cudaGetSymbolAddress((void**)&nh,   d_nbh_h);
    cudaGetSymbolAddress((void**)&ch,   d_cen_h);
    cudaGetSymbolAddress((void**)&gH,   d_gH);
    cudaGetSymbolAddress((void**)&cH,   d_cH);
    cudaGetSymbolAddress((void**)&wc,   d_wcomb);
    cudaGetSymbolAddress((void**)&w2h,  d_w2h);

    cudaFuncSetAttribute(conv_tc, cudaFuncAttributeMaxDynamicSharedMemorySize, CONV_SMEM);

    // NCHW -> NHWC fp16 for both inputs + weight prep, one launch (z: 8 transpose slices + 1 prep)
    transpose_prep<<<dim3(HWS/32, CHC/32, 9), dim3(32, 8)>>>(nbh, cen, nh, ch, w1, w2, wc, w2h);

    // HMMA dual conv: grid (2-row tile, batch, conv); 8 warps, warp tile M64xN32
    conv_tc<<<dim3(HH/2, BB, 2), 256, CONV_SMEM>>>(nh, ch, wc, gH, cH);

    // 4 px/warp, 8 warps/block -> 32 px/block; writes NCHW directly
    fused_attn<<<BB*HWS/32, 256>>>(gH, cH, nh, mv, b1, w2h, b2, out);
}